// round 9
// baseline (speedup 1.0000x reference)
#include <cuda_runtime.h>
#include <float.h>

#define NB 2048
#define NS 200
#define NSP 208      // padded positions
#define ND 64
#define NH 4
#define NH1 64
#define NH2 32
#define NF 256
#define KST 212      // transposed keys row stride (multiple of 4 -> float4-aligned)
#define H1ST 224     // H1P row stride (covers swizzled cols up to 220)
#define NTHR 224     // 7 warps; 208 active compute threads (26 tm x 8 tn)

// Split layer-1 weights (built once per launch)
__device__ float g_W1a[NH*ND*NH1];   // Wk + Wd
__device__ float g_W1b[NH*ND*NH1];   // Wkq
__device__ float g_W1c[NH*ND*NH1];   // Wq - Wd
__device__ float g_C1[NB*NH*NH1];    // per-batch layer-1 bias: q@(Wq-Wd)+b1

__global__ void prep_kernel(const float* __restrict__ W1) {
    int idx = blockIdx.x * blockDim.x + threadIdx.x;   // NH*ND*NH1 = 16384
    if (idx >= NH*ND*NH1) return;
    int j = idx & 63;
    int i = (idx >> 6) & 63;
    int h = idx >> 12;
    const float* w = W1 + h*NF*NH1;
    float wk  = w[(i      )*NH1 + j];
    float wq  = w[(64 + i )*NH1 + j];
    float wkq = w[(128 + i)*NH1 + j];
    float wd  = w[(192 + i)*NH1 + j];
    g_W1a[idx] = wk + wd;
    g_W1b[idx] = wkq;
    g_W1c[idx] = wq - wd;
}

// c1[b][h][j] = b1[h][j] + sum_i q[b][i] * W1c[h][i][j], 32 batches per block
__global__ void prep2_kernel(const float* __restrict__ query, const float* __restrict__ b1) {
    __shared__ float sq[32*64];
    int tid = threadIdx.x;
    int b0 = blockIdx.x * 32;
    for (int t = tid; t < 32*64; t += 256) sq[t] = query[b0*64 + t];
    __syncthreads();
    int h = tid >> 6, j = tid & 63;
    float bias = b1[h*64 + j];
    float acc[32];
    #pragma unroll
    for (int bb = 0; bb < 32; bb++) acc[bb] = bias;
    const float* wcol = g_W1c + h*4096 + j;
    #pragma unroll 4
    for (int i = 0; i < 64; i++) {
        float wv = wcol[i*64];
        #pragma unroll
        for (int bb = 0; bb < 32; bb++) acc[bb] = fmaf(sq[bb*64 + i], wv, acc[bb]);
    }
    for (int bb = 0; bb < 32; bb++) g_C1[(b0+bb)*256 + tid] = acc[bb];
}

// ---- packed f32x2 helpers ----
__device__ __forceinline__ void ffma2(unsigned long long &d, unsigned long long a, unsigned long long b) {
    asm("fma.rn.f32x2 %0, %1, %2, %0;" : "+l"(d) : "l"(a), "l"(b));
}
__device__ __forceinline__ unsigned long long bcast2(float x) {
    unsigned long long r;
    asm("mov.b64 %0, {%1, %1};" : "=l"(r) : "f"(x));
    return r;
}
__device__ __forceinline__ float2 unpack2(unsigned long long v) {
    float lo, hi;
    asm("mov.b64 {%0, %1}, %2;" : "=f"(lo), "=f"(hi) : "l"(v));
    return make_float2(lo, hi);
}

// Shared memory layout (floats), all offsets multiples of 4 (16B-aligned).
#define OFF_W1AB 0                       // 16384
#define OFF_W2   16384                   // 8192
#define OFF_K    24576                   // 64*212 = 13568
#define OFF_H1P  38144                   // 64*224 = 14336 (transposed h1 [n][s^swz])
#define OFF_SC   52480                   // 4*208 = 832
#define OFF_C1   53312                   // 256
#define OFF_Q    53568                   // 64
#define OFF_W3   53632                   // 128
#define OFF_B2   53760                   // 128
#define OFF_OUTH 53888                   // 256
#define OFF_MASK 54144                   // 208
#define OFF_MISC 54352                   // b3[0..3] a1[4..7] a2[8..11] comb[16..79]
#define SMEM_FLOATS 54448                // 217792 bytes

__global__ __launch_bounds__(NTHR, 1)
void attn_main(const float* __restrict__ query,
               const float* __restrict__ keys,
               const int*   __restrict__ kmask,
               const float* __restrict__ a1,
               const float* __restrict__ W2,
               const float* __restrict__ b2,
               const float* __restrict__ a2,
               const float* __restrict__ W3,
               const float* __restrict__ b3,
               const float* __restrict__ Wo,
               const float* __restrict__ bo,
               float* __restrict__ out)
{
    extern __shared__ float sm[];
    float* sW1ab = sm + OFF_W1AB;
    float* sW2   = sm + OFF_W2;
    float* sK    = sm + OFF_K;
    float* sH1P  = sm + OFF_H1P;
    float* sSc   = sm + OFF_SC;
    float* sC1   = sm + OFF_C1;
    float* sQ    = sm + OFF_Q;
    float* sW3   = sm + OFF_W3;
    float* sB2   = sm + OFF_B2;
    float* sOutH = sm + OFF_OUTH;
    float* sMask = sm + OFF_MASK;
    float* sMisc = sm + OFF_MISC;

    const int b   = blockIdx.x;
    const int tid = threadIdx.x;

    // ---- Phase A: cooperative loads ----
    for (int t = tid; t < NH*NH1*NH2; t += NTHR) sW2[t] = W2[t];
    for (int t = tid; t < NH*NH1; t += NTHR) sC1[t] = g_C1[b*256 + t];
    if (tid < NH*NH2) { sW3[tid] = W3[tid]; sB2[tid] = b2[tid]; }
    if (tid < ND) sQ[tid] = query[b*ND + tid];
    if (tid < NH) { sMisc[tid] = b3[tid]; sMisc[4+tid] = a1[tid]; sMisc[8+tid] = a2[tid]; }
    if (tid < NSP) {
        float v = 0.f;
        if (tid < NS) v = (kmask[b*NS + tid] != 0) ? 1.f : 0.f;
        sMask[tid] = v;
    }
    // keys -> transposed smem sK[d][s]; zero pad columns
    if (tid < ND) {
        float* row = sK + tid*KST;
        #pragma unroll
        for (int p = NS; p < KST; p++) row[p] = 0.f;
    }
    const float4* kg = (const float4*)(keys + (size_t)b * (NS*ND));
    for (int t = tid; t < (NS*ND)/4; t += NTHR) {
        float4 v = kg[t];
        int e = t * 4;
        int s = e >> 6;
        int d = e & 63;
        float* dst = sK + d*KST + s;
        dst[0*KST] = v.x; dst[1*KST] = v.y; dst[2*KST] = v.z; dst[3*KST] = v.w;
    }
    __syncthreads();

    // ---- Phase B: fold q into layer-1 weights, PERMUTED per row:
    //   logical col n -> pos ((n>>2)&1)*32 + (n>>3)*4 + (n&3)
    for (int t = tid; t < NH*ND*NH1; t += NTHR) {
        int n = t & 63;
        int i = (t >> 6) & 63;
        int h = t >> 12;
        int pn = ((n >> 2) & 1)*32 + (n >> 3)*4 + (n & 3);
        sW1ab[h*4096 + i*64 + pn] = fmaf(sQ[i], g_W1b[t], g_W1a[t]);
    }
    __syncthreads();

    // ---- Phase C: per-head GEMM1 (8s x 8n tiles) -> PReLU -> GEMM2 -> scores ----
    const bool act = (tid < 208);
    const int tmr = tid >> 3;        // 0..27 (26,27 inactive)
    const int tm  = (tmr > 25) ? 25 : tmr;   // clamp: inactive threads shadow tile 25 (all accesses in-region)
    const int tn  = tid & 7;
    const int s0a = tm * 4;          // first s-block
    const int s0b = 104 + tm * 4;    // second s-block
    const int n8  = tn * 8;          // logical N offset (GEMM1)
    const int n4  = tn * 4;          // permuted word offset / GEMM2 N offset
    const int swz = tn * 4;          // H1P col XOR key for own rows (n>>3 == tn)

    #pragma unroll 1
    for (int h = 0; h < NH; h++) {
        const float al1 = sMisc[4+h];
        const float al2 = sMisc[8+h];

        // --- GEMM1: accA/accB[m][j] = 2 s-blocks x 4 s x 8 n (packed) ---
        unsigned long long accA[4][4], accB[4][4];
        {
            const ulonglong2* cp = (const ulonglong2*)(sC1 + h*NH1 + n8);
            ulonglong2 c0 = cp[0], c1v = cp[1];
            #pragma unroll
            for (int m = 0; m < 4; m++) {
                accA[m][0] = c0.x; accA[m][1] = c0.y; accA[m][2] = c1v.x; accA[m][3] = c1v.y;
                accB[m][0] = c0.x; accB[m][1] = c0.y; accB[m][2] = c1v.x; accB[m][3] = c1v.y;
            }
        }
        {
            const float* wb = sW1ab + h*(ND*NH1);
            const float* ka_p = sK + s0a;
            const float* kb_p = sK + s0b;
            #pragma unroll 4
            for (int k = 0; k < ND; k++) {
                float4 ka = *(const float4*)(ka_p + k*KST);
                float4 kb = *(const float4*)(kb_p + k*KST);
                ulonglong2 w01 = *(const ulonglong2*)(wb + k*NH1 + n4);
                ulonglong2 w23 = *(const ulonglong2*)(wb + k*NH1 + 32 + n4);
                unsigned long long a0 = bcast2(ka.x), a1r = bcast2(ka.y),
                                   a2r = bcast2(ka.z), a3 = bcast2(ka.w);
                ffma2(accA[0][0], a0,  w01.x); ffma2(accA[0][1], a0,  w01.y);
                ffma2(accA[0][2], a0,  w23.x); ffma2(accA[0][3], a0,  w23.y);
                ffma2(accA[1][0], a1r, w01.x); ffma2(accA[1][1], a1r, w01.y);
                ffma2(accA[1][2], a1r, w23.x); ffma2(accA[1][3], a1r, w23.y);
                ffma2(accA[2][0], a2r, w01.x); ffma2(accA[2][1], a2r, w01.y);
                ffma2(accA[2][2], a2r, w23.x); ffma2(accA[2][3], a2r, w23.y);
                ffma2(accA[3][0], a3,  w01.x); ffma2(accA[3][1], a3,  w01.y);
                ffma2(accA[3][2], a3,  w23.x); ffma2(accA[3][3], a3,  w23.y);
                unsigned long long b0 = bcast2(kb.x), b1r = bcast2(kb.y),
                                   b2r = bcast2(kb.z), b3v = bcast2(kb.w);
                ffma2(accB[0][0], b0,  w01.x); ffma2(accB[0][1], b0,  w01.y);
                ffma2(accB[0][2], b0,  w23.x); ffma2(accB[0][3], b0,  w23.y);
                ffma2(accB[1][0], b1r, w01.x); ffma2(accB[1][1], b1r, w01.y);
                ffma2(accB[1][2], b1r, w23.x); ffma2(accB[1][3], b1r, w23.y);
                ffma2(accB[2][0], b2r, w01.x); ffma2(accB[2][1], b2r, w01.y);
                ffma2(accB[2][2], b2r, w23.x); ffma2(accB[2][3], b2r, w23.y);
                ffma2(accB[3][0], b3v, w01.x); ffma2(accB[3][1], b3v, w01.y);
                ffma2(accB[3][2], b3v, w23.x); ffma2(accB[3][3], b3v, w23.y);
            }
        }
        // PReLU1 + transposed store: H1P[n][s ^ ((n>>3)*4)]
        if (act) {
            #pragma unroll
            for (int j = 0; j < 4; j++) {
                #pragma unroll
                for (int p = 0; p < 2; p++) {
                    const int n = n8 + 2*j + p;
                    float4 va, vb;
                    float x;
                    x = p ? unpack2(accA[0][j]).y : unpack2(accA[0][j]).x; va.x = x > 0.f ? x : al1*x;
                    x = p ? unpack2(accA[1][j]).y : unpack2(accA[1][j]).x; va.y = x > 0.f ? x : al1*x;
                    x = p ? unpack2(accA[2][j]).y : unpack2(accA[2][j]).x; va.z = x > 0.f ? x : al1*x;
                    x = p ? unpack2(accA[3][j]).y : unpack2(accA[3][j]).x; va.w = x > 0.f ? x : al1*x;
                    x = p ? unpack2(accB[0][j]).y : unpack2(accB[0][j]).x; vb.x = x > 0.f ? x : al1*x;
                    x = p ? unpack2(accB[1][j]).y : unpack2(accB[1][j]).x; vb.y = x > 0.f ? x : al1*x;
                    x = p ? unpack2(accB[2][j]).y : unpack2(accB[2][j]).x; vb.z = x > 0.f ? x : al1*x;
                    x = p ? unpack2(accB[3][j]).y : unpack2(accB[3][j]).x; vb.w = x > 0.f ? x : al1*x;
                    *(float4*)(sH1P + n*H1ST + (s0a ^ swz)) = va;
                    *(float4*)(sH1P + n*H1ST + (s0b ^ swz)) = vb;
                }
            }
        }
        __syncthreads();

        // --- GEMM2: acc2A/B[m][jj] = 2 s-blocks x 4 s x 4 n (packed) ---
        unsigned long long acc2A[4][2], acc2B[4][2];
        {
            ulonglong2 bb = *(const ulonglong2*)(sB2 + h*NH2 + n4);
            #pragma unroll
            for (int m = 0; m < 4; m++) {
                acc2A[m][0] = bb.x; acc2A[m][1] = bb.y;
                acc2B[m][0] = bb.x; acc2B[m][1] = bb.y;
            }
        }
        {
            const float* w2b = sW2 + h*(NH1*NH2) + n4;
            #pragma unroll 4
            for (int k = 0; k < NH1; k++) {
                const int key = (k >> 3) * 4;
                float4 ha = *(const float4*)(sH1P + k*H1ST + (s0a ^ key));
                float4 hb = *(const float4*)(sH1P + k*H1ST + (s0b ^ key));
                ulonglong2 wv = *(const ulonglong2*)(w2b + k*NH2);
                unsigned long long h0 = bcast2(ha.x), h1v = bcast2(ha.y),
                                   h2 = bcast2(ha.z), h3 = bcast2(ha.w);
                ffma2(acc2A[0][0], h0,  wv.x); ffma2(acc2A[0][1], h0,  wv.y);
                ffma2(acc2A[1][0], h1v, wv.x); ffma2(acc2A[1][1], h1v, wv.y);
                ffma2(acc2A[2][0], h2,  wv.x); ffma2(acc2A[2][1], h2,  wv.y);
                ffma2(acc2A[3][0], h3,  wv.x); ffma2(acc2A[3][1], h3,  wv.y);
                unsigned long long g0 = bcast2(hb.x), g1 = bcast2(hb.y),
                                   g2 = bcast2(hb.z), g3 = bcast2(hb.w);
                ffma2(acc2B[0][0], g0, wv.x); ffma2(acc2B[0][1], g0, wv.y);
                ffma2(acc2B[1][0], g1, wv.x); ffma2(acc2B[1][1], g1, wv.y);
                ffma2(acc2B[2][0], g2, wv.x); ffma2(acc2B[2][1], g2, wv.y);
                ffma2(acc2B[3][0], g3, wv.x); ffma2(acc2B[3][1], g3, wv.y);
            }
        }
        // PReLU2 + layer-3 partial dot + 8-lane reduce -> scores
        {
            float4 w3v = *(const float4*)(sW3 + h*NH2 + n4);
            float part[8];
            #pragma unroll
            for (int m = 0; m < 4; m++) {
                float2 v0 = unpack2(acc2A[m][0]);
                float2 v1 = unpack2(acc2A[m][1]);
                float x0 = v0.x > 0.f ? v0.x : al2*v0.x;
                float x1 = v0.y > 0.f ? v0.y : al2*v0.y;
                float x2 = v1.x > 0.f ? v1.x : al2*v1.x;
                float x3 = v1.y > 0.f ? v1.y : al2*v1.y;
                part[m] = x0*w3v.x + x1*w3v.y + x2*w3v.z + x3*w3v.w;
                float2 u0 = unpack2(acc2B[m][0]);
                float2 u1 = unpack2(acc2B[m][1]);
                float y0 = u0.x > 0.f ? u0.x : al2*u0.x;
                float y1 = u0.y > 0.f ? u0.y : al2*u0.y;
                float y2 = u1.x > 0.f ? u1.x : al2*u1.x;
                float y3 = u1.y > 0.f ? u1.y : al2*u1.y;
                part[4+m] = y0*w3v.x + y1*w3v.y + y2*w3v.z + y3*w3v.w;
            }
            #pragma unroll
            for (int off = 1; off < 8; off <<= 1) {
                #pragma unroll
                for (int m = 0; m < 8; m++)
                    part[m] += __shfl_xor_sync(0xffffffffu, part[m], off);
            }
            if (act && tn == 0) {
                float b3h = sMisc[h];
                #pragma unroll
                for (int m = 0; m < 4; m++) {
                    int sa = s0a + m, sb = s0b + m;
                    sSc[h*NSP + sa] = (sMask[sa] != 0.f) ? (part[m]   + b3h) : -FLT_MAX;
                    sSc[h*NSP + sb] = (sMask[sb] != 0.f) ? (part[4+m] + b3h) : -FLT_MAX;
                }
            }
        }
        __syncthreads();
    }

    // ---- Phase D: masked softmax per head (warps 0-3, all full) ----
    {
        int warp = tid >> 5, lane = tid & 31;
        if (warp < NH) {
            float* row = sSc + warp*NSP;
            float m = -FLT_MAX;
            for (int t = lane; t < NS; t += 32) m = fmaxf(m, row[t]);
            #pragma unroll
            for (int o = 16; o > 0; o >>= 1) m = fmaxf(m, __shfl_xor_sync(0xffffffffu, m, o));
            float sum = 0.f;
            for (int t = lane; t < NS; t += 32) {
                float v = row[t];
                float e = (v > -1e38f) ? expf(v - m) : 0.f;
                row[t] = e;
                sum += e;
            }
            #pragma unroll
            for (int o = 16; o > 0; o >>= 1) sum += __shfl_xor_sync(0xffffffffu, sum, o);
            float inv = (sum > 0.f) ? (1.f / sum) : 0.f;
            for (int t = lane; t < NS; t += 32) row[t] *= inv;
        }
    }
    __syncthreads();

    // ---- Phase E: weighted sum over keys, head mean, output projection ----
    for (int t = tid; t < NH*ND; t += NTHR) {
        int h = t >> 6, d = t & 63;
        const float* w    = sSc + h*NSP;
        const float* kcol = sK + d*KST;
        float a0 = 0.f, a1_ = 0.f, a2_ = 0.f, a3_ = 0.f;
        #pragma unroll 4
        for (int tt = 0; tt < NS; tt += 4) {
            a0  = fmaf(w[tt  ], kcol[tt  ], a0);
            a1_ = fmaf(w[tt+1], kcol[tt+1], a1_);
            a2_ = fmaf(w[tt+2], kcol[tt+2], a2_);
            a3_ = fmaf(w[tt+3], kcol[tt+3], a3_);
        }
        sOutH[h*ND + d] = (a0 + a1_) + (a2_ + a3_);
    }
    __syncthreads();
    if (tid < ND) {
        float c = 0.25f * (sOutH[tid] + sOutH[64+tid] + sOutH[128+tid] + sOutH[192+tid]);
        sMisc[16 + tid] = c;
    }
    __syncthreads();
    if (tid < ND) {
        float e0 = bo[tid], e1 = 0.f;
        #pragma unroll 4
        for (int d2 = 0; d2 < ND; d2 += 2) {
            e0 = fmaf(sMisc[16 + d2],     Wo[(d2  )*ND + tid], e0);
            e1 = fmaf(sMisc[16 + d2 + 1], Wo[(d2+1)*ND + tid], e1);
        }
        out[b*ND + tid] = e0 + e1;
    }
}

extern "C" void kernel_launch(void* const* d_in, const int* in_sizes, int n_in,
                              void* d_out, int out_size) {
    const float* query = (const float*)d_in[0];
    const float* keys  = (const float*)d_in[1];
    const int*   kmask = (const int*)  d_in[2];
    const float* W1    = (const float*)d_in[3];
    const float* b1    = (const float*)d_in[4];
    const float* a1    = (const float*)d_in[5];
    const float* W2    = (const float*)d_in[6];
    const float* b2    = (const float*)d_in[7];
    const float* a2    = (const float*)d_in[8];
    const float* W3    = (const float*)d_in[9];
    const float* b3    = (const float*)d_in[10];
    const float* Wo    = (const float*)d_in[11];
    const float* bo    = (const float*)d_in[12];
    float* out = (float*)d_out;

    cudaFuncSetAttribute(attn_main, cudaFuncAttributeMaxDynamicSharedMemorySize,
                         SMEM_FLOATS * (int)sizeof(float));

    prep_kernel<<<64, 256>>>(W1);
    prep2_kernel<<<64, 256>>>(query, b1);
    attn_main<<<NB, NTHR, SMEM_FLOATS * sizeof(float)>>>(
        query, keys, kmask, a1, W2, b2, a2, W3, b3, Wo, bo, out);
}

// round 10
// speedup vs baseline: 1.1202x; 1.1202x over previous
#include <cuda_runtime.h>
#include <float.h>

#define NB 2048
#define NS 200
#define NSP 208      // padded positions
#define ND 64
#define NH 4
#define NH1 64
#define NH2 32
#define NF 256
#define KST 212      // transposed keys row stride (multiple of 4 -> float4-aligned)
#define NTHR 224     // 7 warps/CTA; 2 CTAs/SM -> 14 warps/SM

// Split layer-1 weights (built once per launch)
__device__ float g_W1a[NH*ND*NH1];   // Wk + Wd
__device__ float g_W1b[NH*ND*NH1];   // Wkq
__device__ float g_W1c[NH*ND*NH1];   // Wq - Wd
__device__ float g_C1[NB*NH*NH1];    // per-batch layer-1 bias: q@(Wq-Wd)+b1

__global__ void prep_kernel(const float* __restrict__ W1) {
    int idx = blockIdx.x * blockDim.x + threadIdx.x;   // NH*ND*NH1 = 16384
    if (idx >= NH*ND*NH1) return;
    int j = idx & 63;
    int i = (idx >> 6) & 63;
    int h = idx >> 12;
    const float* w = W1 + h*NF*NH1;
    float wk  = w[(i      )*NH1 + j];
    float wq  = w[(64 + i )*NH1 + j];
    float wkq = w[(128 + i)*NH1 + j];
    float wd  = w[(192 + i)*NH1 + j];
    g_W1a[idx] = wk + wd;
    g_W1b[idx] = wkq;
    g_W1c[idx] = wq - wd;
}

// c1[b][h][j] = b1[h][j] + sum_i q[b][i] * W1c[h][i][j], 32 batches per block
__global__ void prep2_kernel(const float* __restrict__ query, const float* __restrict__ b1) {
    __shared__ float sq[32*64];
    int tid = threadIdx.x;
    int b0 = blockIdx.x * 32;
    for (int t = tid; t < 32*64; t += 256) sq[t] = query[b0*64 + t];
    __syncthreads();
    int h = tid >> 6, j = tid & 63;
    float bias = b1[h*64 + j];
    float acc[32];
    #pragma unroll
    for (int bb = 0; bb < 32; bb++) acc[bb] = bias;
    const float* wcol = g_W1c + h*4096 + j;
    #pragma unroll 4
    for (int i = 0; i < 64; i++) {
        float wv = wcol[i*64];
        #pragma unroll
        for (int bb = 0; bb < 32; bb++) acc[bb] = fmaf(sq[bb*64 + i], wv, acc[bb]);
    }
    for (int bb = 0; bb < 32; bb++) g_C1[(b0+bb)*256 + tid] = acc[bb];
}

// ---- packed f32x2 helpers ----
__device__ __forceinline__ void ffma2(unsigned long long &d, unsigned long long a, unsigned long long b) {
    asm("fma.rn.f32x2 %0, %1, %2, %0;" : "+l"(d) : "l"(a), "l"(b));
}
__device__ __forceinline__ void fadd2(unsigned long long &d, unsigned long long a) {
    asm("add.rn.f32x2 %0, %0, %1;" : "+l"(d) : "l"(a));
}
__device__ __forceinline__ unsigned long long bcast2(float x) {
    unsigned long long r;
    asm("mov.b64 %0, {%1, %1};" : "=l"(r) : "f"(x));
    return r;
}
__device__ __forceinline__ unsigned long long pack2(float x, float y) {
    unsigned long long r;
    asm("mov.b64 %0, {%1, %2};" : "=l"(r) : "f"(x), "f"(y));
    return r;
}
__device__ __forceinline__ float2 unpack2(unsigned long long v) {
    float lo, hi;
    asm("mov.b64 {%0, %1}, %2;" : "=f"(lo), "=f"(hi) : "l"(v));
    return make_float2(lo, hi);
}

// Shared memory layout (floats), all offsets multiples of 4 (16B-aligned).
#define OFF_W1H  0                       // 4096  current-head folded W1 (permuted cols)
#define OFF_W2   4096                    // 8192  plain [h][n][j]
#define OFF_K    12288                   // 64*212 = 13568
#define OFF_SC   25856                   // 4*208 = 832
#define OFF_C1   26688                   // 256
#define OFF_Q    26944                   // 64
#define OFF_W3   27008                   // 128
#define OFF_B2   27136                   // 128
#define OFF_OUTH 27264                   // 256
#define OFF_MASK 27520                   // 208
#define OFF_MISC 27728                   // 96
#define SMEM_FLOATS 27824                // 111296 bytes -> 2 CTAs/SM

__global__ __launch_bounds__(NTHR, 2)
void attn_main(const float* __restrict__ query,
               const float* __restrict__ keys,
               const int*   __restrict__ kmask,
               const float* __restrict__ a1,
               const float* __restrict__ W2,
               const float* __restrict__ b2,
               const float* __restrict__ a2,
               const float* __restrict__ W3,
               const float* __restrict__ b3,
               const float* __restrict__ Wo,
               const float* __restrict__ bo,
               float* __restrict__ out)
{
    extern __shared__ float sm[];
    float* sW1h  = sm + OFF_W1H;
    float* sW2   = sm + OFF_W2;
    float* sK    = sm + OFF_K;
    float* sSc   = sm + OFF_SC;
    float* sC1   = sm + OFF_C1;
    float* sQ    = sm + OFF_Q;
    float* sW3   = sm + OFF_W3;
    float* sB2   = sm + OFF_B2;
    float* sOutH = sm + OFF_OUTH;
    float* sMask = sm + OFF_MASK;
    float* sMisc = sm + OFF_MISC;

    const int b   = blockIdx.x;
    const int tid = threadIdx.x;

    // ---- Phase A: cooperative loads ----
    for (int t = tid; t < NH*NH1*NH2; t += NTHR) sW2[t] = W2[t];
    for (int t = tid; t < NH*NH1; t += NTHR) sC1[t] = g_C1[b*256 + t];
    if (tid < NH*NH2) { sW3[tid] = W3[tid]; sB2[tid] = b2[tid]; }
    if (tid < ND) sQ[tid] = query[b*ND + tid];
    if (tid < NH) { sMisc[tid] = b3[tid]; sMisc[4+tid] = a1[tid]; sMisc[8+tid] = a2[tid]; }
    if (tid < NSP) {
        float v = 0.f;
        if (tid < NS) v = (kmask[b*NS + tid] != 0) ? 1.f : 0.f;
        sMask[tid] = v;
    }
    // keys -> transposed smem sK[d][s]; zero pad columns
    if (tid < ND) {
        float* row = sK + tid*KST;
        #pragma unroll
        for (int p = NS; p < KST; p++) row[p] = 0.f;
    }
    const float4* kg = (const float4*)(keys + (size_t)b * (NS*ND));
    for (int t = tid; t < (NS*ND)/4; t += NTHR) {
        float4 v = kg[t];
        int e = t * 4;
        int s = e >> 6;
        int d = e & 63;
        float* dst = sK + d*KST + s;
        dst[0*KST] = v.x; dst[1*KST] = v.y; dst[2*KST] = v.z; dst[3*KST] = v.w;
    }

    // ---- Phase C: per-head [build W1h] -> GEMM1 (8s x 8n) -> PReLU ->
    //      rotation-GEMM2 (shfl, no smem staging) -> scores ----
    const bool act = (tid < 208);
    const int tmr = tid >> 3;
    const int tm  = (tmr > 25) ? 25 : tmr;   // inactive threads shadow tile 25
    const int tn  = tid & 7;
    const int lanebase = (tid & 31) & ~7;    // 8-lane group base within warp
    const int s0a = tm * 4;
    const int s0b = 104 + tm * 4;
    const int n8  = tn * 8;                  // logical n offset
    const int n4  = tn * 4;                  // permuted word offset / own j offset

    #pragma unroll 1
    for (int h = 0; h < NH; h++) {
        __syncthreads();   // Phase A done (h=0) / sW1h no longer read (h>0)
        // build folded W1 for head h, PERMUTED cols: n -> ((n>>2)&1)*32 + (n>>3)*4 + (n&3)
        for (int t = tid; t < ND*NH1; t += NTHR) {
            int n = t & 63;
            int i = t >> 6;
            int pn = ((n >> 2) & 1)*32 + ((n >> 3) << 2) + (n & 3);
            sW1h[i*64 + pn] = fmaf(sQ[i], g_W1b[h*4096 + t], g_W1a[h*4096 + t]);
        }
        __syncthreads();

        const float al1 = sMisc[4+h];
        const float al2 = sMisc[8+h];

        // --- GEMM1: accA/accB[m][j] = 2 s-blocks x 4 s x 8 n (packed) ---
        unsigned long long accA[4][4], accB[4][4];
        {
            const ulonglong2* cp = (const ulonglong2*)(sC1 + h*NH1 + n8);
            ulonglong2 c0 = cp[0], c1v = cp[1];
            #pragma unroll
            for (int m = 0; m < 4; m++) {
                accA[m][0] = c0.x; accA[m][1] = c0.y; accA[m][2] = c1v.x; accA[m][3] = c1v.y;
                accB[m][0] = c0.x; accB[m][1] = c0.y; accB[m][2] = c1v.x; accB[m][3] = c1v.y;
            }
        }
        {
            const float* ka_p = sK + s0a;
            const float* kb_p = sK + s0b;
            #pragma unroll 4
            for (int k = 0; k < ND; k++) {
                float4 ka = *(const float4*)(ka_p + k*KST);
                float4 kb = *(const float4*)(kb_p + k*KST);
                ulonglong2 w01 = *(const ulonglong2*)(sW1h + k*NH1 + n4);
                ulonglong2 w23 = *(const ulonglong2*)(sW1h + k*NH1 + 32 + n4);
                unsigned long long a0 = bcast2(ka.x), a1r = bcast2(ka.y),
                                   a2r = bcast2(ka.z), a3 = bcast2(ka.w);
                ffma2(accA[0][0], a0,  w01.x); ffma2(accA[0][1], a0,  w01.y);
                ffma2(accA[0][2], a0,  w23.x); ffma2(accA[0][3], a0,  w23.y);
                ffma2(accA[1][0], a1r, w01.x); ffma2(accA[1][1], a1r, w01.y);
                ffma2(accA[1][2], a1r, w23.x); ffma2(accA[1][3], a1r, w23.y);
                ffma2(accA[2][0], a2r, w01.x); ffma2(accA[2][1], a2r, w01.y);
                ffma2(accA[2][2], a2r, w23.x); ffma2(accA[2][3], a2r, w23.y);
                ffma2(accA[3][0], a3,  w01.x); ffma2(accA[3][1], a3,  w01.y);
                ffma2(accA[3][2], a3,  w23.x); ffma2(accA[3][3], a3,  w23.y);
                unsigned long long b0 = bcast2(kb.x), b1r = bcast2(kb.y),
                                   b2r = bcast2(kb.z), b3v = bcast2(kb.w);
                ffma2(accB[0][0], b0,  w01.x); ffma2(accB[0][1], b0,  w01.y);
                ffma2(accB[0][2], b0,  w23.x); ffma2(accB[0][3], b0,  w23.y);
                ffma2(accB[1][0], b1r, w01.x); ffma2(accB[1][1], b1r, w01.y);
                ffma2(accB[1][2], b1r, w23.x); ffma2(accB[1][3], b1r, w23.y);
                ffma2(accB[2][0], b2r, w01.x); ffma2(accB[2][1], b2r, w01.y);
                ffma2(accB[2][2], b2r, w23.x); ffma2(accB[2][3], b2r, w23.y);
                ffma2(accB[3][0], b3v, w01.x); ffma2(accB[3][1], b3v, w01.y);
                ffma2(accB[3][2], b3v, w23.x); ffma2(accB[3][3], b3v, w23.y);
            }
        }
        // --- PReLU1 in place (packed): acc* become h1 ---
        #pragma unroll
        for (int m = 0; m < 4; m++) {
            #pragma unroll
            for (int j = 0; j < 4; j++) {
                float2 v = unpack2(accA[m][j]);
                v.x = v.x > 0.f ? v.x : al1*v.x;
                v.y = v.y > 0.f ? v.y : al1*v.y;
                accA[m][j] = pack2(v.x, v.y);
                float2 u = unpack2(accB[m][j]);
                u.x = u.x > 0.f ? u.x : al1*u.x;
                u.y = u.y > 0.f ? u.y : al1*u.y;
                accB[m][j] = pack2(u.x, u.y);
            }
        }

        // --- rotation-GEMM2: each round r, compute partial for lane (tn+r)&7's
        //     j-range using my 8-n slice, shfl to owner, accumulate. ---
        unsigned long long acc2A[4][2], acc2B[4][2];
        {
            ulonglong2 bb = *(const ulonglong2*)(sB2 + h*NH2 + n4);
            #pragma unroll
            for (int m = 0; m < 4; m++) {
                acc2A[m][0] = bb.x; acc2A[m][1] = bb.y;
                acc2B[m][0] = bb.x; acc2B[m][1] = bb.y;
            }
        }
        {
            const float* w2h = sW2 + h*(NH1*NH2);
            #pragma unroll 1
            for (int r = 0; r < 8; r++) {
                const int jd = ((tn + r) & 7) << 2;
                const int src = lanebase | ((tn - r) & 7);
                ulonglong2 w2v[8];
                #pragma unroll
                for (int nl = 0; nl < 8; nl++)
                    w2v[nl] = *(const ulonglong2*)(w2h + (n8 + nl)*NH2 + jd);
                // block A partial
                unsigned long long p[4][2];
                #pragma unroll
                for (int m = 0; m < 4; m++) { p[m][0] = 0ull; p[m][1] = 0ull; }
                #pragma unroll
                for (int nl = 0; nl < 8; nl++) {
                    #pragma unroll
                    for (int m = 0; m < 4; m++) {
                        float2 hp = unpack2(accA[m][nl >> 1]);
                        unsigned long long hv = bcast2((nl & 1) ? hp.y : hp.x);
                        ffma2(p[m][0], hv, w2v[nl].x);
                        ffma2(p[m][1], hv, w2v[nl].y);
                    }
                }
                if (r == 0) {
                    #pragma unroll
                    for (int m = 0; m < 4; m++) { fadd2(acc2A[m][0], p[m][0]); fadd2(acc2A[m][1], p[m][1]); }
                } else {
                    #pragma unroll
                    for (int m = 0; m < 4; m++) {
                        unsigned long long q0 = __shfl_sync(0xffffffffu, p[m][0], src);
                        unsigned long long q1 = __shfl_sync(0xffffffffu, p[m][1], src);
                        fadd2(acc2A[m][0], q0); fadd2(acc2A[m][1], q1);
                    }
                }
                // block B partial
                #pragma unroll
                for (int m = 0; m < 4; m++) { p[m][0] = 0ull; p[m][1] = 0ull; }
                #pragma unroll
                for (int nl = 0; nl < 8; nl++) {
                    #pragma unroll
                    for (int m = 0; m < 4; m++) {
                        float2 hp = unpack2(accB[m][nl >> 1]);
                        unsigned long long hv = bcast2((nl & 1) ? hp.y : hp.x);
                        ffma2(p[m][0], hv, w2v[nl].x);
                        ffma2(p[m][1], hv, w2v[nl].y);
                    }
                }
                if (r == 0) {
                    #pragma unroll
                    for (int m = 0; m < 4; m++) { fadd2(acc2B[m][0], p[m][0]); fadd2(acc2B[m][1], p[m][1]); }
                } else {
                    #pragma unroll
                    for (int m = 0; m < 4; m++) {
                        unsigned long long q0 = __shfl_sync(0xffffffffu, p[m][0], src);
                        unsigned long long q1 = __shfl_sync(0xffffffffu, p[m][1], src);
                        fadd2(acc2B[m][0], q0); fadd2(acc2B[m][1], q1);
                    }
                }
            }
        }
        // --- PReLU2 + layer-3 partial dot + 8-lane reduce -> scores ---
        {
            float4 w3v = *(const float4*)(sW3 + h*NH2 + n4);
            float part[8];
            #pragma unroll
            for (int m = 0; m < 4; m++) {
                float2 v0 = unpack2(acc2A[m][0]);
                float2 v1 = unpack2(acc2A[m][1]);
                float x0 = v0.x > 0.f ? v0.x : al2*v0.x;
                float x1 = v0.y > 0.f ? v0.y : al2*v0.y;
                float x2 = v1.x > 0.f ? v1.x : al2*v1.x;
                float x3 = v1.y > 0.f ? v1.y : al2*v1.y;
                part[m] = x0*w3v.x + x1*w3v.y + x2*w3v.z + x3*w3v.w;
                float2 u0 = unpack2(acc2B[m][0]);
                float2 u1 = unpack2(acc2B[m][1]);
                float y0 = u0.x > 0.f ? u0.x : al2*u0.x;
                float y1 = u0.y > 0.f ? u0.y : al2*u0.y;
                float y2 = u1.x > 0.f ? u1.x : al2*u1.x;
                float y3 = u1.y > 0.f ? u1.y : al2*u1.y;
                part[4+m] = y0*w3v.x + y1*w3v.y + y2*w3v.z + y3*w3v.w;
            }
            #pragma unroll
            for (int off = 1; off < 8; off <<= 1) {
                #pragma unroll
                for (int m = 0; m < 8; m++)
                    part[m] += __shfl_xor_sync(0xffffffffu, part[m], off);
            }
            if (act && tn == 0) {
                float b3h = sMisc[h];
                #pragma unroll
                for (int m = 0; m < 4; m++) {
                    int sa = s0a + m, sb = s0b + m;
                    sSc[h*NSP + sa] = (sMask[sa] != 0.f) ? (part[m]   + b3h) : -FLT_MAX;
                    sSc[h*NSP + sb] = (sMask[sb] != 0.f) ? (part[4+m] + b3h) : -FLT_MAX;
                }
            }
        }
    }
    __syncthreads();

    // ---- Phase D: masked softmax per head (warps 0-3) ----
    {
        int warp = tid >> 5, lane = tid & 31;
        if (warp < NH) {
            float* row = sSc + warp*NSP;
            float m = -FLT_MAX;
            for (int t = lane; t < NS; t += 32) m = fmaxf(m, row[t]);
            #pragma unroll
            for (int o = 16; o > 0; o >>= 1) m = fmaxf(m, __shfl_xor_sync(0xffffffffu, m, o));
            float sum = 0.f;
            for (int t = lane; t < NS; t += 32) {
                float v = row[t];
                float e = (v > -1e38f) ? expf(v - m) : 0.f;
                row[t] = e;
                sum += e;
            }
            #pragma unroll
            for (int o = 16; o > 0; o >>= 1) sum += __shfl_xor_sync(0xffffffffu, sum, o);
            float inv = (sum > 0.f) ? (1.f / sum) : 0.f;
            for (int t = lane; t < NS; t += 32) row[t] *= inv;
        }
    }
    __syncthreads();

    // ---- Phase E: weighted sum over keys, head mean, output projection ----
    for (int t = tid; t < NH*ND; t += NTHR) {
        int h = t >> 6, d = t & 63;
        const float* w    = sSc + h*NSP;
        const float* kcol = sK + d*KST;
        float a0 = 0.f, a1_ = 0.f, a2_ = 0.f, a3_ = 0.f;
        #pragma unroll 4
        for (int tt = 0; tt < NS; tt += 4) {
            a0  = fmaf(w[tt  ], kcol[tt  ], a0);
            a1_ = fmaf(w[tt+1], kcol[tt+1], a1_);
            a2_ = fmaf(w[tt+2], kcol[tt+2], a2_);
            a3_ = fmaf(w[tt+3], kcol[tt+3], a3_);
        }
        sOutH[h*ND + d] = (a0 + a1_) + (a2_ + a3_);
    }
    __syncthreads();
    if (tid < ND) {
        float c = 0.25f * (sOutH[tid] + sOutH[64+tid] + sOutH[128+tid] + sOutH[192+tid]);
        sMisc[16 + tid] = c;
    }
    __syncthreads();
    if (tid < ND) {
        float e0 = bo[tid], e1 = 0.f;
        #pragma unroll 4
        for (int d2 = 0; d2 < ND; d2 += 2) {
            e0 = fmaf(sMisc[16 + d2],     Wo[(d2  )*ND + tid], e0);
            e1 = fmaf(sMisc[16 + d2 + 1], Wo[(d2+1)*ND + tid], e1);
        }
        out[b*ND + tid] = e0 + e1;
    }
}

extern "C" void kernel_launch(void* const* d_in, const int* in_sizes, int n_in,
                              void* d_out, int out_size) {
    const float* query = (const float*)d_in[0];
    const float* keys  = (const float*)d_in[1];
    const int*   kmask = (const int*)  d_in[2];
    const float* W1    = (const float*)d_in[3];
    const float* b1    = (const float*)d_in[4];
    const float* a1    = (const float*)d_in[5];
    const float* W2    = (const float*)d_in[6];
    const float* b2    = (const float*)d_in[7];
    const float* a2    = (const float*)d_in[8];
    const float* W3    = (const float*)d_in[9];
    const float* b3    = (const float*)d_in[10];
    const float* Wo    = (const float*)d_in[11];
    const float* bo    = (const float*)d_in[12];
    float* out = (float*)d_out;

    cudaFuncSetAttribute(attn_main, cudaFuncAttributeMaxDynamicSharedMemorySize,
                         SMEM_FLOATS * (int)sizeof(float));

    prep_kernel<<<64, 256>>>(W1);
    prep2_kernel<<<64, 256>>>(query, b1);
    attn_main<<<NB, NTHR, SMEM_FLOATS * sizeof(float)>>>(
        query, keys, kmask, a1, W2, b2, a2, W3, b3, Wo, bo, out);
}

// round 12
// speedup vs baseline: 1.6163x; 1.4428x over previous
#include <cuda_runtime.h>
#include <cuda_bf16.h>
#include <float.h>
#include <stdint.h>

#define NB 2048
#define NS 200
#define NSP 208
#define ND 64
#define NH 4
#define NH1 64
#define NH2 32
#define KST 212
#define NTHR 256
#define RST 72        // padded row stride (elements) for all bf16 MMA tiles: conflict-free frags

// ---- global prep buffers ----
__device__ float g_W1aT[16384];           // (Wk+Wd)^T  [n=h*64+j][k]
__device__ float g_W1bT[16384];           // Wkq^T      [n][k]
__device__ float g_W1c[16384];            // Wq-Wd      [h][k][j] (for c1 prep)
__device__ __nv_bfloat16 g_B2hi[128*RST]; // W2^T hi    [n=h*32+j][k] padded rows
__device__ __nv_bfloat16 g_B2lo[128*RST];
__device__ float g_C1[NB*256];            // c1 = q@(Wq-Wd)+b1

__global__ void prep_w1(const float* __restrict__ W1) {
    int e = blockIdx.x*256 + threadIdx.x;           // 0..16383
    if (e >= 16384) return;
    int k = e & 63;
    int n = e >> 6;
    int h = n >> 6, j = n & 63;
    const float* w = W1 + h*256*64;
    g_W1aT[e] = w[k*64+j] + w[(192+k)*64+j];
    g_W1bT[e] = w[(128+k)*64+j];
    g_W1c[h*4096 + k*64 + j] = w[(64+k)*64+j] - w[(192+k)*64+j];
}

__global__ void prep_w2(const float* __restrict__ W2) {
    int e = blockIdx.x*256 + threadIdx.x;           // over 128*RST = 9216
    if (e >= 128*RST) return;
    int k = e % RST;
    int n = e / RST;
    if (k >= 64) { g_B2hi[e] = __float2bfloat16(0.f); g_B2lo[e] = __float2bfloat16(0.f); return; }
    int h = n >> 5, j = n & 31;
    float v = W2[h*2048 + k*32 + j];
    __nv_bfloat16 hi = __float2bfloat16(v);
    g_B2hi[e] = hi;
    g_B2lo[e] = __float2bfloat16(v - __bfloat162float(hi));
}

__global__ void prep_c1(const float* __restrict__ query, const float* __restrict__ b1) {
    __shared__ float sq[32*64];
    int tid = threadIdx.x;
    int b0 = blockIdx.x * 32;
    for (int t = tid; t < 32*64; t += 256) sq[t] = query[b0*64 + t];
    __syncthreads();
    int h = tid >> 6, j = tid & 63;
    float bias = b1[h*64 + j];
    float acc[32];
    #pragma unroll
    for (int bb = 0; bb < 32; bb++) acc[bb] = bias;
    const float* wcol = g_W1c + h*4096 + j;
    #pragma unroll 4
    for (int i = 0; i < 64; i++) {
        float wv = wcol[i*64];
        #pragma unroll
        for (int bb = 0; bb < 32; bb++) acc[bb] = fmaf(sq[bb*64 + i], wv, acc[bb]);
    }
    for (int bb = 0; bb < 32; bb++) g_C1[(b0+bb)*256 + tid] = acc[bb];
}

// ---- helpers ----
__device__ __forceinline__ uint32_t pkbf(__nv_bfloat16 a, __nv_bfloat16 b) {
    __nv_bfloat162 t = __halves2bfloat162(a, b);
    return *reinterpret_cast<uint32_t*>(&t);
}
__device__ __forceinline__ void split2(float x, float y, uint32_t& hi, uint32_t& lo) {
    __nv_bfloat16 hx = __float2bfloat16(x), hy = __float2bfloat16(y);
    hi = pkbf(hx, hy);
    lo = pkbf(__float2bfloat16(x - __bfloat162float(hx)),
              __float2bfloat16(y - __bfloat162float(hy)));
}
__device__ __forceinline__ void mma16816(float* d, const uint32_t* a, const uint32_t* b) {
    asm volatile("mma.sync.aligned.m16n8k16.row.col.f32.bf16.bf16.f32 "
        "{%0,%1,%2,%3}, {%4,%5,%6,%7}, {%8,%9}, {%0,%1,%2,%3};"
        : "+f"(d[0]), "+f"(d[1]), "+f"(d[2]), "+f"(d[3])
        : "r"(a[0]), "r"(a[1]), "r"(a[2]), "r"(a[3]), "r"(b[0]), "r"(b[1]));
}

// ---- smem layout (bytes) ----
#define SM_AHI   0          // keys hi [s=256][RST] bf16 = 36864
#define SM_ALO   36864
#define SM_B1HI  73728      // W1ab^T hi [n=256][RST]
#define SM_B1LO  110592
#define SM_B2HI  147456     // W2^T hi [n=128][RST] = 18432
#define SM_B2LO  165888
#define SM_SC    184320     // 4*208 f32
#define SM_C1    187648     // 256 f32
#define SM_MASK  188672     // 208 f32 (+pad)
#define SM_W3    189504     // 128 f32
#define SM_B2B   190016     // 128 f32
#define SM_MISC  190528     // b3[0..3] a1[4..7] a2[8..11] comb[16..79]
#define SM_Q     190912     // 64 f32
#define SM_OUTH  191168     // 256 f32
#define SMEM_BYTES 192192
// Phase E reuses [0 .. 54272) (dead A-tile region) for fp32 keys [64][KST]

__global__ __launch_bounds__(NTHR, 1)
void attn_main(const float* __restrict__ query,
               const float* __restrict__ keys,
               const int*   __restrict__ kmask,
               const float* __restrict__ a1,
               const float* __restrict__ b2,
               const float* __restrict__ a2,
               const float* __restrict__ W3,
               const float* __restrict__ b3,
               const float* __restrict__ Wo,
               const float* __restrict__ bo,
               float* __restrict__ out)
{
    extern __shared__ char smc[];
    float* sScf  = (float*)(smc + SM_SC);
    float* sC1f  = (float*)(smc + SM_C1);
    float* sMaskf= (float*)(smc + SM_MASK);
    float* sW3f  = (float*)(smc + SM_W3);
    float* sB2bf = (float*)(smc + SM_B2B);
    float* sMiscf= (float*)(smc + SM_MISC);
    float* sQf   = (float*)(smc + SM_Q);
    float* sOutH = (float*)(smc + SM_OUTH);
    float* sKf   = (float*)(smc);          // Phase E only

    const int b = blockIdx.x;
    const int tid = threadIdx.x;
    const int wid = tid >> 5, lane = tid & 31;
    const int gr = lane >> 2, gc = lane & 3;

    // ---- Phase A ----
    for (int t = tid; t < 256; t += NTHR) sC1f[t] = g_C1[b*256 + t];
    if (tid < NH*NH2) { sW3f[tid] = W3[tid]; sB2bf[tid] = b2[tid]; }
    if (tid < ND) sQf[tid] = query[b*ND + tid];
    if (tid < NH) { sMiscf[tid] = b3[tid]; sMiscf[4+tid] = a1[tid]; sMiscf[8+tid] = a2[tid]; }
    if (tid < NSP) {
        float v = 0.f;
        if (tid < NS) v = (kmask[b*NS + tid] != 0) ? 1.f : 0.f;
        sMaskf[tid] = v;
    }
    // copy prepped B2 tiles
    for (int t = tid; t < 1152; t += NTHR) {
        ((uint4*)(smc+SM_B2HI))[t] = ((const uint4*)g_B2hi)[t];
        ((uint4*)(smc+SM_B2LO))[t] = ((const uint4*)g_B2lo)[t];
    }
    // zero A rows 200..255 (both parts): (256-200)*144 = 8064B = 504 uint4
    for (int t = tid; t < 504; t += NTHR) {
        ((uint4*)(smc + SM_AHI + 200*144))[t] = make_uint4(0,0,0,0);
        ((uint4*)(smc + SM_ALO + 200*144))[t] = make_uint4(0,0,0,0);
    }
    // keys -> split A tiles [s][k] stride RST
    {
        const float4* kg = (const float4*)(keys + (size_t)b * (NS*ND));
        for (int t = tid; t < 3200; t += NTHR) {
            float4 v = kg[t];
            int e = t*4, s = e>>6, k = e&63;
            uint32_t h01, l01, h23, l23;
            split2(v.x, v.y, h01, l01);
            split2(v.z, v.w, h23, l23);
            uint32_t off = (uint32_t)(s*RST + k) * 2u;
            *(uint2*)(smc + SM_AHI + off) = make_uint2(h01, h23);
            *(uint2*)(smc + SM_ALO + off) = make_uint2(l01, l23);
        }
    }
    __syncthreads();   // sQf ready for fold

    // B1 fold: W1ab^T[n][k] = W1aT + q_k * W1bT, split, stride RST
    for (int t = tid; t < 16384; t += NTHR) {
        int k = t & 63, n = t >> 6;
        float va = fmaf(sQf[k], g_W1bT[t], g_W1aT[t]);
        __nv_bfloat16 ha = __float2bfloat16(va);
        uint32_t off = (uint32_t)(n*RST + k) * 2u;
        *(__nv_bfloat16*)(smc + SM_B1HI + off) = ha;
        *(__nv_bfloat16*)(smc + SM_B1LO + off) =
            __float2bfloat16(va - __bfloat162float(ha));
    }
    __syncthreads();

    // ---- load A fragments once (reused for all heads) ----
    uint32_t ahi[2][4][4], alo[2][4][4];
    {
        const int row0 = wid*32;
        #pragma unroll
        for (int m = 0; m < 2; m++) {
            int rbase = row0 + m*16 + gr;
            #pragma unroll
            for (int kc = 0; kc < 4; kc++) {
                uint32_t e00 = (uint32_t)(rbase*RST + kc*16 + 2*gc) * 2u;
                uint32_t e10 = e00 + 8u*RST*2u;
                ahi[m][kc][0] = *(const uint32_t*)(smc + SM_AHI + e00);
                ahi[m][kc][1] = *(const uint32_t*)(smc + SM_AHI + e10);
                ahi[m][kc][2] = *(const uint32_t*)(smc + SM_AHI + e00 + 16);
                ahi[m][kc][3] = *(const uint32_t*)(smc + SM_AHI + e10 + 16);
                alo[m][kc][0] = *(const uint32_t*)(smc + SM_ALO + e00);
                alo[m][kc][1] = *(const uint32_t*)(smc + SM_ALO + e10);
                alo[m][kc][2] = *(const uint32_t*)(smc + SM_ALO + e00 + 16);
                alo[m][kc][3] = *(const uint32_t*)(smc + SM_ALO + e10 + 16);
            }
        }
    }

    // ---- Phase C: per-head GEMM1 -> epilogue -> GEMM2 -> scores ----
    #pragma unroll 1
    for (int h = 0; h < NH; h++) {
        const float al1 = sMiscf[4+h];
        const float al2 = sMiscf[8+h];

        float acc[2][8][4];
        #pragma unroll
        for (int m = 0; m < 2; m++)
            #pragma unroll
            for (int nf = 0; nf < 8; nf++)
                #pragma unroll
                for (int r = 0; r < 4; r++) acc[m][nf][r] = 0.f;

        // 3 passes: (Ahi,B1hi), (Ahi,B1lo), (Alo,B1hi)
        #pragma unroll 1
        for (int pass = 0; pass < 3; pass++) {
            const char* bbase = smc + ((pass == 1) ? SM_B1LO : SM_B1HI);
            #pragma unroll
            for (int kc = 0; kc < 4; kc++) {
                uint32_t bf[8][2];
                #pragma unroll
                for (int nf = 0; nf < 8; nf++) {
                    uint32_t e = (uint32_t)((h*64 + nf*8 + gr)*RST + kc*16 + 2*gc) * 2u;
                    bf[nf][0] = *(const uint32_t*)(bbase + e);
                    bf[nf][1] = *(const uint32_t*)(bbase + e + 16);
                }
                const uint32_t (*A)[4][4] = (pass == 2) ? alo : ahi;
                #pragma unroll
                for (int m = 0; m < 2; m++)
                    #pragma unroll
                    for (int nf = 0; nf < 8; nf++)
                        mma16816(acc[m][nf], A[m][kc], bf[nf]);
            }
        }

        // epilogue 1: +c1, PReLU -> split into A2 fragments (C->A remap)
        uint32_t a2h[2][4][4], a2l[2][4][4];
        #pragma unroll
        for (int m = 0; m < 2; m++) {
            #pragma unroll
            for (int nf = 0; nf < 8; nf++) {
                float2 c1v = *(const float2*)(sC1f + h*64 + nf*8 + 2*gc);
                float v0 = acc[m][nf][0] + c1v.x;
                float v1 = acc[m][nf][1] + c1v.y;
                float v2 = acc[m][nf][2] + c1v.x;
                float v3 = acc[m][nf][3] + c1v.y;
                acc[m][nf][0] = v0 > 0.f ? v0 : al1*v0;
                acc[m][nf][1] = v1 > 0.f ? v1 : al1*v1;
                acc[m][nf][2] = v2 > 0.f ? v2 : al1*v2;
                acc[m][nf][3] = v3 > 0.f ? v3 : al1*v3;
            }
            #pragma unroll
            for (int kc = 0; kc < 4; kc++) {
                const float* cA = acc[m][2*kc];
                const float* cB = acc[m][2*kc+1];
                split2(cA[0], cA[1], a2h[m][kc][0], a2l[m][kc][0]);
                split2(cA[2], cA[3], a2h[m][kc][1], a2l[m][kc][1]);
                split2(cB[0], cB[1], a2h[m][kc][2], a2l[m][kc][2]);
                split2(cB[2], cB[3], a2h[m][kc][3], a2l[m][kc][3]);
            }
        }

        // GEMM2: acc2[2m][4n]
        float acc2[2][4][4];
        #pragma unroll
        for (int m = 0; m < 2; m++)
            #pragma unroll
            for (int nf = 0; nf < 4; nf++)
                #pragma unroll
                for (int r = 0; r < 4; r++) acc2[m][nf][r] = 0.f;

        #pragma unroll 1
        for (int pass = 0; pass < 3; pass++) {
            const char* bbase = smc + ((pass == 1) ? SM_B2LO : SM_B2HI);
            const uint32_t (*A)[4][4] = (pass == 2) ? a2l : a2h;
            #pragma unroll
            for (int kc = 0; kc < 4; kc++) {
                uint32_t bf[4][2];
                #pragma unroll
                for (int nf = 0; nf < 4; nf++) {
                    uint32_t e = (uint32_t)((h*32 + nf*8 + gr)*RST + kc*16 + 2*gc) * 2u;
                    bf[nf][0] = *(const uint32_t*)(bbase + e);
                    bf[nf][1] = *(const uint32_t*)(bbase + e + 16);
                }
                #pragma unroll
                for (int m = 0; m < 2; m++)
                    #pragma unroll
                    for (int nf = 0; nf < 4; nf++)
                        mma16816(acc2[m][nf], A[m][kc], bf[nf]);
            }
        }

        // epilogue 2: +b2, PReLU, dot W3, 4-lane reduce -> scores
        const float b3h = sMiscf[h];
        #pragma unroll
        for (int m = 0; m < 2; m++) {
            float p0 = 0.f, p1 = 0.f;
            #pragma unroll
            for (int nf = 0; nf < 4; nf++) {
                int j0 = h*32 + nf*8 + 2*gc;
                float2 bb = *(const float2*)(sB2bf + j0);
                float2 ww = *(const float2*)(sW3f + j0);
                float v0 = acc2[m][nf][0] + bb.x;
                float v1 = acc2[m][nf][1] + bb.y;
                float v2 = acc2[m][nf][2] + bb.x;
                float v3 = acc2[m][nf][3] + bb.y;
                v0 = v0 > 0.f ? v0 : al2*v0;
                v1 = v1 > 0.f ? v1 : al2*v1;
                v2 = v2 > 0.f ? v2 : al2*v2;
                v3 = v3 > 0.f ? v3 : al2*v3;
                p0 = fmaf(v0, ww.x, fmaf(v1, ww.y, p0));
                p1 = fmaf(v2, ww.x, fmaf(v3, ww.y, p1));
            }
            p0 += __shfl_xor_sync(0xffffffffu, p0, 1);
            p0 += __shfl_xor_sync(0xffffffffu, p0, 2);
            p1 += __shfl_xor_sync(0xffffffffu, p1, 1);
            p1 += __shfl_xor_sync(0xffffffffu, p1, 2);
            if (gc == 0) {
                int s = wid*32 + m*16 + gr;
                if (s < NSP)   sScf[h*NSP + s]   = (sMaskf[s]   != 0.f) ? (p0 + b3h) : -FLT_MAX;
                if (s+8 < NSP) sScf[h*NSP + s+8] = (sMaskf[s+8] != 0.f) ? (p1 + b3h) : -FLT_MAX;
            }
        }
    }
    __syncthreads();

    // ---- Phase D (warps 0-3) overlapped with fp32-keys reload (warps 4-7) ----
    if (wid < NH) {
        float* row = sScf + wid*NSP;
        float m = -FLT_MAX;
        for (int t = lane; t < NS; t += 32) m = fmaxf(m, row[t]);
        #pragma unroll
        for (int o = 16; o > 0; o >>= 1) m = fmaxf(m, __shfl_xor_sync(0xffffffffu, m, o));
        float sum = 0.f;
        for (int t = lane; t < NS; t += 32) {
            float v = row[t];
            float e = (v > -1e38f) ? expf(v - m) : 0.f;
            row[t] = e;
            sum += e;
        }
        #pragma unroll
        for (int o = 16; o > 0; o >>= 1) sum += __shfl_xor_sync(0xffffffffu, sum, o);
        float inv = (sum > 0.f) ? (1.f / sum) : 0.f;
        for (int t = lane; t < NS; t += 32) row[t] *= inv;
    } else {
        int t2 = tid - 128;
        for (int t = t2; t < 768; t += 128) {      // pad cols 200..211
            int d = t / 12, p = 200 + t % 12;
            sKf[d*KST + p] = 0.f;
        }
        const float4* kg = (const float4*)(keys + (size_t)b * (NS*ND));
        for (int t = t2; t < 3200; t += 128) {
            float4 v = kg[t];
            int e = t*4, s = e>>6, d = e&63;
            float* dst = sKf + d*KST + s;
            dst[0*KST]=v.x; dst[1*KST]=v.y; dst[2*KST]=v.z; dst[3*KST]=v.w;
        }
    }
    __syncthreads();

    // ---- Phase E: weighted sum, head mean, out projection ----
    {
        int h = tid >> 6, d = tid & 63;
        const float* w    = sScf + h*NSP;
        const float* kcol = sKf + d*KST;
        float a0 = 0.f, a1_ = 0.f, a2_ = 0.f, a3_ = 0.f;
        #pragma unroll 4
        for (int t = 0; t < NS; t += 4) {
            a0  = fmaf(w[t  ], kcol[t  ], a0);
            a1_ = fmaf(w[t+1], kcol[t+1], a1_);
            a2_ = fmaf(w[t+2], kcol[t+2], a2_);
            a3_ = fmaf(w[t+3], kcol[t+3], a3_);
        }
        sOutH[tid] = (a0 + a1_) + (a2_ + a3_);
    }
    __syncthreads();
    if (tid < ND) {
        float c = 0.25f * (sOutH[tid] + sOutH[64+tid] + sOutH[128+tid] + sOutH[192+tid]);
        sMiscf[16 + tid] = c;
    }
    __syncthreads();
    if (tid < ND) {
        float e0 = bo[tid], e1 = 0.f;
        #pragma unroll 4
        for (int d2 = 0; d2 < ND; d2 += 2) {
            e0 = fmaf(sMiscf[16 + d2],     Wo[(d2  )*ND + tid], e0);
            e1 = fmaf(sMiscf[16 + d2 + 1], Wo[(d2+1)*ND + tid], e1);
        }
        out[b*ND + tid] = e0 + e1;
    }
}

extern "C" void kernel_launch(void* const* d_in, const int* in_sizes, int n_in,
                              void* d_out, int out_size) {
    const float* query = (const float*)d_in[0];
    const float* keys  = (const float*)d_in[1];
    const int*   kmask = (const int*)  d_in[2];
    const float* W1    = (const float*)d_in[3];
    const float* b1    = (const float*)d_in[4];
    const float* a1    = (const float*)d_in[5];
    const float* W2    = (const float*)d_in[6];
    const float* b2    = (const float*)d_in[7];
    const float* a2    = (const float*)d_in[8];
    const float* W3    = (const float*)d_in[9];
    const float* b3    = (const float*)d_in[10];
    const float* Wo    = (const float*)d_in[11];
    const float* bo    = (const float*)d_in[12];
    float* out = (float*)d_out;

    cudaFuncSetAttribute(attn_main, cudaFuncAttributeMaxDynamicSharedMemorySize, SMEM_BYTES);

    prep_w1<<<64, 256>>>(W1);
    prep_w2<<<36, 256>>>(W2);
    prep_c1<<<64, 256>>>(query, b1);
    attn_main<<<NB, NTHR, SMEM_BYTES>>>(
        query, keys, kmask, a1, b2, a2, W3, b3, Wo, bo, out);
}

// round 13
// speedup vs baseline: 1.9122x; 1.1831x over previous
#include <cuda_runtime.h>
#include <cuda_bf16.h>
#include <float.h>
#include <stdint.h>

#define NB 2048
#define NS 200
#define NSP 208
#define ND 64
#define NH 4
#define NH1 64
#define NH2 32
#define KST 212
#define NTHR 512
#define RST 72        // padded row stride (elements) for all bf16 MMA tiles: conflict-free frags

// ---- global prep buffers ----
__device__ float g_W1aT[16384];           // (Wk+Wd)^T  [n=h*64+j][k]
__device__ float g_W1bT[16384];           // Wkq^T      [n][k]
__device__ float g_W1c[16384];            // Wq-Wd      [h][k][j] (for c1 prep)
__device__ __nv_bfloat16 g_B2hi[128*RST]; // W2^T hi    [n=h*32+j][k] padded rows
__device__ __nv_bfloat16 g_B2lo[128*RST];
__device__ float g_C1[NB*256];            // c1 = q@(Wq-Wd)+b1

__global__ void prep_w1(const float* __restrict__ W1) {
    int e = blockIdx.x*256 + threadIdx.x;           // 0..16383
    if (e >= 16384) return;
    int k = e & 63;
    int n = e >> 6;
    int h = n >> 6, j = n & 63;
    const float* w = W1 + h*256*64;
    g_W1aT[e] = w[k*64+j] + w[(192+k)*64+j];
    g_W1bT[e] = w[(128+k)*64+j];
    g_W1c[h*4096 + k*64 + j] = w[(64+k)*64+j] - w[(192+k)*64+j];
}

__global__ void prep_w2(const float* __restrict__ W2) {
    int e = blockIdx.x*256 + threadIdx.x;           // over 128*RST = 9216
    if (e >= 128*RST) return;
    int k = e % RST;
    int n = e / RST;
    if (k >= 64) { g_B2hi[e] = __float2bfloat16(0.f); g_B2lo[e] = __float2bfloat16(0.f); return; }
    int h = n >> 5, j = n & 31;
    float v = W2[h*2048 + k*32 + j];
    __nv_bfloat16 hi = __float2bfloat16(v);
    g_B2hi[e] = hi;
    g_B2lo[e] = __float2bfloat16(v - __bfloat162float(hi));
}

__global__ void prep_c1(const float* __restrict__ query, const float* __restrict__ b1) {
    __shared__ float sq[32*64];
    int tid = threadIdx.x;
    int b0 = blockIdx.x * 32;
    for (int t = tid; t < 32*64; t += 256) sq[t] = query[b0*64 + t];
    __syncthreads();
    int h = tid >> 6, j = tid & 63;
    float bias = b1[h*64 + j];
    float acc[32];
    #pragma unroll
    for (int bb = 0; bb < 32; bb++) acc[bb] = bias;
    const float* wcol = g_W1c + h*4096 + j;
    #pragma unroll 4
    for (int i = 0; i < 64; i++) {
        float wv = wcol[i*64];
        #pragma unroll
        for (int bb = 0; bb < 32; bb++) acc[bb] = fmaf(sq[bb*64 + i], wv, acc[bb]);
    }
    for (int bb = 0; bb < 32; bb++) g_C1[(b0+bb)*256 + tid] = acc[bb];
}

// ---- helpers ----
__device__ __forceinline__ uint32_t pkbf(__nv_bfloat16 a, __nv_bfloat16 b) {
    __nv_bfloat162 t = __halves2bfloat162(a, b);
    return *reinterpret_cast<uint32_t*>(&t);
}
__device__ __forceinline__ void split2(float x, float y, uint32_t& hi, uint32_t& lo) {
    __nv_bfloat16 hx = __float2bfloat16(x), hy = __float2bfloat16(y);
    hi = pkbf(hx, hy);
    lo = pkbf(__float2bfloat16(x - __bfloat162float(hx)),
              __float2bfloat16(y - __bfloat162float(hy)));
}
__device__ __forceinline__ void mma16816(float* d, const uint32_t* a, const uint32_t* b) {
    asm volatile("mma.sync.aligned.m16n8k16.row.col.f32.bf16.bf16.f32 "
        "{%0,%1,%2,%3}, {%4,%5,%6,%7}, {%8,%9}, {%0,%1,%2,%3};"
        : "+f"(d[0]), "+f"(d[1]), "+f"(d[2]), "+f"(d[3])
        : "r"(a[0]), "r"(a[1]), "r"(a[2]), "r"(a[3]), "r"(b[0]), "r"(b[1]));
}

// ---- smem layout (bytes) ----
#define SM_AHI   0          // keys hi [s=256][RST] bf16 = 36864
#define SM_ALO   36864
#define SM_B1HI  73728      // W1ab^T hi [n=256][RST]
#define SM_B1LO  110592
#define SM_B2HI  147456     // W2^T hi [n=128][RST] = 18432
#define SM_B2LO  165888
#define SM_SC    184320     // 4*208 f32
#define SM_C1    187648     // 256 f32
#define SM_MASK  188672     // 208 f32 (+pad)
#define SM_W3    189504     // 128 f32
#define SM_B2B   190016     // 128 f32
#define SM_MISC  190528     // b3[0..3] a1[4..7] a2[8..11] comb[16..79]
#define SM_Q     190912     // 64 f32
#define SM_OUTH  191168     // 256 f32
#define SMEM_BYTES 192192
// Phase E reuses [0 .. 54272) (dead A-tile region) for fp32 keys [64][KST]

__global__ __launch_bounds__(NTHR, 1)
void attn_main(const float* __restrict__ query,
               const float* __restrict__ keys,
               const int*   __restrict__ kmask,
               const float* __restrict__ a1,
               const float* __restrict__ b2,
               const float* __restrict__ a2,
               const float* __restrict__ W3,
               const float* __restrict__ b3,
               const float* __restrict__ Wo,
               const float* __restrict__ bo,
               float* __restrict__ out)
{
    extern __shared__ char smc[];
    float* sScf  = (float*)(smc + SM_SC);
    float* sC1f  = (float*)(smc + SM_C1);
    float* sMaskf= (float*)(smc + SM_MASK);
    float* sW3f  = (float*)(smc + SM_W3);
    float* sB2bf = (float*)(smc + SM_B2B);
    float* sMiscf= (float*)(smc + SM_MISC);
    float* sQf   = (float*)(smc + SM_Q);
    float* sOutH = (float*)(smc + SM_OUTH);
    float* sKf   = (float*)(smc);          // Phase E only

    const int b = blockIdx.x;
    const int tid = threadIdx.x;
    const int wid = tid >> 5, lane = tid & 31;
    const int gr = lane >> 2, gc = lane & 3;

    // ---- Phase A ----
    for (int t = tid; t < 256; t += NTHR) sC1f[t] = g_C1[b*256 + t];
    if (tid < NH*NH2) { sW3f[tid] = W3[tid]; sB2bf[tid] = b2[tid]; }
    if (tid < ND) sQf[tid] = query[b*ND + tid];
    if (tid < NH) { sMiscf[tid] = b3[tid]; sMiscf[4+tid] = a1[tid]; sMiscf[8+tid] = a2[tid]; }
    if (tid < NSP) {
        float v = 0.f;
        if (tid < NS) v = (kmask[b*NS + tid] != 0) ? 1.f : 0.f;
        sMaskf[tid] = v;
    }
    // copy prepped B2 tiles
    for (int t = tid; t < 1152; t += NTHR) {
        ((uint4*)(smc+SM_B2HI))[t] = ((const uint4*)g_B2hi)[t];
        ((uint4*)(smc+SM_B2LO))[t] = ((const uint4*)g_B2lo)[t];
    }
    // zero A rows 200..255 (both parts): (256-200)*144 = 8064B = 504 uint4
    for (int t = tid; t < 504; t += NTHR) {
        ((uint4*)(smc + SM_AHI + 200*144))[t] = make_uint4(0,0,0,0);
        ((uint4*)(smc + SM_ALO + 200*144))[t] = make_uint4(0,0,0,0);
    }
    // keys -> split A tiles [s][k] stride RST
    {
        const float4* kg = (const float4*)(keys + (size_t)b * (NS*ND));
        for (int t = tid; t < 3200; t += NTHR) {
            float4 v = kg[t];
            int e = t*4, s = e>>6, k = e&63;
            uint32_t h01, l01, h23, l23;
            split2(v.x, v.y, h01, l01);
            split2(v.z, v.w, h23, l23);
            uint32_t off = (uint32_t)(s*RST + k) * 2u;
            *(uint2*)(smc + SM_AHI + off) = make_uint2(h01, h23);
            *(uint2*)(smc + SM_ALO + off) = make_uint2(l01, l23);
        }
    }
    __syncthreads();   // sQf ready for fold

    // B1 fold: W1ab^T[n][k] = W1aT + q_k * W1bT, split, stride RST
    for (int t = tid; t < 16384; t += NTHR) {
        int k = t & 63, n = t >> 6;
        float va = fmaf(sQf[k], g_W1bT[t], g_W1aT[t]);
        __nv_bfloat16 ha = __float2bfloat16(va);
        uint32_t off = (uint32_t)(n*RST + k) * 2u;
        *(__nv_bfloat16*)(smc + SM_B1HI + off) = ha;
        *(__nv_bfloat16*)(smc + SM_B1LO + off) =
            __float2bfloat16(va - __bfloat162float(ha));
    }
    __syncthreads();

    // ---- load A fragments once (16 rows per warp; reused for all heads) ----
    uint32_t ahi[4][4], alo[4][4];
    {
        const int rbase = wid*16 + gr;
        #pragma unroll
        for (int kc = 0; kc < 4; kc++) {
            uint32_t e00 = (uint32_t)(rbase*RST + kc*16 + 2*gc) * 2u;
            uint32_t e10 = e00 + 8u*RST*2u;
            ahi[kc][0] = *(const uint32_t*)(smc + SM_AHI + e00);
            ahi[kc][1] = *(const uint32_t*)(smc + SM_AHI + e10);
            ahi[kc][2] = *(const uint32_t*)(smc + SM_AHI + e00 + 16);
            ahi[kc][3] = *(const uint32_t*)(smc + SM_AHI + e10 + 16);
            alo[kc][0] = *(const uint32_t*)(smc + SM_ALO + e00);
            alo[kc][1] = *(const uint32_t*)(smc + SM_ALO + e10);
            alo[kc][2] = *(const uint32_t*)(smc + SM_ALO + e00 + 16);
            alo[kc][3] = *(const uint32_t*)(smc + SM_ALO + e10 + 16);
        }
    }

    // ---- Phase C: per-head GEMM1 -> epilogue -> GEMM2 -> scores ----
    #pragma unroll 1
    for (int h = 0; h < NH; h++) {
        const float al1 = sMiscf[4+h];
        const float al2 = sMiscf[8+h];

        float acc[8][4];
        #pragma unroll
        for (int nf = 0; nf < 8; nf++)
            #pragma unroll
            for (int r = 0; r < 4; r++) acc[nf][r] = 0.f;

        // 3 passes: (Ahi,B1hi), (Ahi,B1lo), (Alo,B1hi)
        #pragma unroll 1
        for (int pass = 0; pass < 3; pass++) {
            const char* bbase = smc + ((pass == 1) ? SM_B1LO : SM_B1HI);
            const uint32_t (*A)[4] = (pass == 2) ? alo : ahi;
            #pragma unroll
            for (int kc = 0; kc < 4; kc++) {
                uint32_t bf[8][2];
                #pragma unroll
                for (int nf = 0; nf < 8; nf++) {
                    uint32_t e = (uint32_t)((h*64 + nf*8 + gr)*RST + kc*16 + 2*gc) * 2u;
                    bf[nf][0] = *(const uint32_t*)(bbase + e);
                    bf[nf][1] = *(const uint32_t*)(bbase + e + 16);
                }
                #pragma unroll
                for (int nf = 0; nf < 8; nf++)
                    mma16816(acc[nf], A[kc], bf[nf]);
            }
        }

        // epilogue 1: +c1, PReLU -> split into A2 fragments (C->A remap)
        uint32_t a2h[4][4], a2l[4][4];
        #pragma unroll
        for (int nf = 0; nf < 8; nf++) {
            float2 c1v = *(const float2*)(sC1f + h*64 + nf*8 + 2*gc);
            float v0 = acc[nf][0] + c1v.x;
            float v1 = acc[nf][1] + c1v.y;
            float v2 = acc[nf][2] + c1v.x;
            float v3 = acc[nf][3] + c1v.y;
            acc[nf][0] = v0 > 0.f ? v0 : al1*v0;
            acc[nf][1] = v1 > 0.f ? v1 : al1*v1;
            acc[nf][2] = v2 > 0.f ? v2 : al1*v2;
            acc[nf][3] = v3 > 0.f ? v3 : al1*v3;
        }
        #pragma unroll
        for (int kc = 0; kc < 4; kc++) {
            const float* cA = acc[2*kc];
            const float* cB = acc[2*kc+1];
            split2(cA[0], cA[1], a2h[kc][0], a2l[kc][0]);
            split2(cA[2], cA[3], a2h[kc][1], a2l[kc][1]);
            split2(cB[0], cB[1], a2h[kc][2], a2l[kc][2]);
            split2(cB[2], cB[3], a2h[kc][3], a2l[kc][3]);
        }

        // GEMM2: acc2[4n]
        float acc2[4][4];
        #pragma unroll
        for (int nf = 0; nf < 4; nf++)
            #pragma unroll
            for (int r = 0; r < 4; r++) acc2[nf][r] = 0.f;

        #pragma unroll 1
        for (int pass = 0; pass < 3; pass++) {
            const char* bbase = smc + ((pass == 1) ? SM_B2LO : SM_B2HI);
            const uint32_t (*A)[4] = (pass == 2) ? a2l : a2h;
            #pragma unroll
            for (int kc = 0; kc < 4; kc++) {
                uint32_t bf[4][2];
                #pragma unroll
                for (int nf = 0; nf < 4; nf++) {
                    uint32_t e = (uint32_t)((h*32 + nf*8 + gr)*RST + kc*16 + 2*gc) * 2u;
                    bf[nf][0] = *(const uint32_t*)(bbase + e);
                    bf[nf][1] = *(const uint32_t*)(bbase + e + 16);
                }
                #pragma unroll
                for (int nf = 0; nf < 4; nf++)
                    mma16816(acc2[nf], A[kc], bf[nf]);
            }
        }

        // epilogue 2: +b2, PReLU, dot W3, 4-lane reduce -> scores
        const float b3h = sMiscf[h];
        {
            float p0 = 0.f, p1 = 0.f;
            #pragma unroll
            for (int nf = 0; nf < 4; nf++) {
                int j0 = h*32 + nf*8 + 2*gc;
                float2 bb = *(const float2*)(sB2bf + j0);
                float2 ww = *(const float2*)(sW3f + j0);
                float v0 = acc2[nf][0] + bb.x;
                float v1 = acc2[nf][1] + bb.y;
                float v2 = acc2[nf][2] + bb.x;
                float v3 = acc2[nf][3] + bb.y;
                v0 = v0 > 0.f ? v0 : al2*v0;
                v1 = v1 > 0.f ? v1 : al2*v1;
                v2 = v2 > 0.f ? v2 : al2*v2;
                v3 = v3 > 0.f ? v3 : al2*v3;
                p0 = fmaf(v0, ww.x, fmaf(v1, ww.y, p0));
                p1 = fmaf(v2, ww.x, fmaf(v3, ww.y, p1));
            }
            p0 += __shfl_xor_sync(0xffffffffu, p0, 1);
            p0 += __shfl_xor_sync(0xffffffffu, p0, 2);
            p1 += __shfl_xor_sync(0xffffffffu, p1, 1);
            p1 += __shfl_xor_sync(0xffffffffu, p1, 2);
            if (gc == 0) {
                int s = wid*16 + gr;
                if (s < NSP)   sScf[h*NSP + s]   = (sMaskf[s]   != 0.f) ? (p0 + b3h) : -FLT_MAX;
                if (s+8 < NSP) sScf[h*NSP + s+8] = (sMaskf[s+8] != 0.f) ? (p1 + b3h) : -FLT_MAX;
            }
        }
    }
    __syncthreads();

    // ---- Phase D (warps 0-3) overlapped with fp32-keys reload (warps 4-15) ----
    if (wid < NH) {
        float* row = sScf + wid*NSP;
        float m = -FLT_MAX;
        for (int t = lane; t < NS; t += 32) m = fmaxf(m, row[t]);
        #pragma unroll
        for (int o = 16; o > 0; o >>= 1) m = fmaxf(m, __shfl_xor_sync(0xffffffffu, m, o));
        float sum = 0.f;
        for (int t = lane; t < NS; t += 32) {
            float v = row[t];
            float e = (v > -1e38f) ? expf(v - m) : 0.f;
            row[t] = e;
            sum += e;
        }
        #pragma unroll
        for (int o = 16; o > 0; o >>= 1) sum += __shfl_xor_sync(0xffffffffu, sum, o);
        float inv = (sum > 0.f) ? (1.f / sum) : 0.f;
        for (int t = lane; t < NS; t += 32) row[t] *= inv;
    } else {
        int t2 = tid - 128;                        // 0..383
        for (int t = t2; t < 768; t += 384) {      // pad cols 200..211
            int d = t / 12, p = 200 + t % 12;
            sKf[d*KST + p] = 0.f;
        }
        const float4* kg = (const float4*)(keys + (size_t)b * (NS*ND));
        for (int t = t2; t < 3200; t += 384) {
            float4 v = kg[t];
            int e = t*4, s = e>>6, d = e&63;
            float* dst = sKf + d*KST + s;
            dst[0*KST]=v.x; dst[1*KST]=v.y; dst[2*KST]=v.z; dst[3*KST]=v.w;
        }
    }
    __syncthreads();

    // ---- Phase E: weighted sum, head mean, out projection ----
    if (tid < NH*ND) {
        int h = tid >> 6, d = tid & 63;
        const float* w    = sScf + h*NSP;
        const float* kcol = sKf + d*KST;
        float a0 = 0.f, a1_ = 0.f, a2_ = 0.f, a3_ = 0.f;
        #pragma unroll 4
        for (int t = 0; t < NS; t += 4) {
            a0  = fmaf(w[t  ], kcol[t  ], a0);
            a1_ = fmaf(w[t+1], kcol[t+1], a1_);
            a2_ = fmaf(w[t+2], kcol[t+2], a2_);
            a3_ = fmaf(w[t+3], kcol[t+3], a3_);
        }
        sOutH[tid] = (a0 + a1_) + (a2_ + a3_);
    }
    __syncthreads();
    if (tid < ND) {
        float c = 0.25f * (sOutH[tid] + sOutH[64+tid] + sOutH[128+tid] + sOutH[192+tid]);
        sMiscf[16 + tid] = c;
    }
    __syncthreads();
    if (tid < ND) {
        float e0 = bo[tid], e1 = 0.f;
        #pragma unroll 4
        for (int d2 = 0; d2 < ND; d2 += 2) {
            e0 = fmaf(sMiscf[16 + d2],     Wo[(d2  )*ND + tid], e0);
            e1 = fmaf(sMiscf[16 + d2 + 1], Wo[(d2+1)*ND + tid], e1);
        }
        out[b*ND + tid] = e0 + e1;
    }
}

extern "C" void kernel_launch(void* const* d_in, const int* in_sizes, int n_in,
                              void* d_out, int out_size) {
    const float* query = (const float*)d_in[0];
    const float* keys  = (const float*)d_in[1];
    const int*   kmask = (const int*)  d_in[2];
    const float* W1    = (const float*)d_in[3];
    const float* b1    = (const float*)d_in[4];
    const float* a1    = (const float*)d_in[5];
    const float* W2    = (const float*)d_in[6];
    const float* b2    = (const float*)d_in[7];
    const float* a2    = (const float*)d_in[8];
    const float* W3    = (const float*)d_in[9];
    const float* b3    = (const float*)d_in[10];
    const float* Wo    = (const float*)d_in[11];
    const float* bo    = (const float*)d_in[12];
    float* out = (float*)d_out;

    cudaFuncSetAttribute(attn_main, cudaFuncAttributeMaxDynamicSharedMemorySize, SMEM_BYTES);

    prep_w1<<<64, 256>>>(W1);
    prep_w2<<<36, 256>>>(W2);
    prep_c1<<<64, 256>>>(query, b1);
    attn_main<<<NB, NTHR, SMEM_BYTES>>>(
        query, keys, kmask, a1, b2, a2, W3, b3, Wo, bo, out);
}

// round 14
// speedup vs baseline: 1.9553x; 1.0226x over previous
#include <cuda_runtime.h>
#include <cuda_bf16.h>
#include <float.h>
#include <stdint.h>

#define NB 2048
#define NS 200
#define NSP 208
#define ND 64
#define NH 4
#define NH1 64
#define NH2 32
#define KST 212
#define NTHR 512
#define RST 72        // padded row stride (elements) for all bf16 MMA tiles

// ---- global prep buffers ----
__device__ float g_W1aT[16384];           // (Wk+Wd)^T  [n=h*64+j][k]
__device__ float g_W1bT[16384];           // Wkq^T      [n][k]
__device__ float g_W1c[16384];            // Wq-Wd      [h][k][j] (for c1 prep)
__device__ __nv_bfloat16 g_B2hi[128*RST]; // W2^T hi    [n=h*32+j][k] padded rows
__device__ __nv_bfloat16 g_B2lo[128*RST];
__device__ float g_C1[NB*256];            // c1 = q@(Wq-Wd)+b1

__global__ void prep_w1(const float* __restrict__ W1) {
    int e = blockIdx.x*256 + threadIdx.x;           // 0..16383
    if (e >= 16384) return;
    int k = e & 63;
    int n = e >> 6;
    int h = n >> 6, j = n & 63;
    const float* w = W1 + h*256*64;
    g_W1aT[e] = w[k*64+j] + w[(192+k)*64+j];
    g_W1bT[e] = w[(128+k)*64+j];
    g_W1c[h*4096 + k*64 + j] = w[(64+k)*64+j] - w[(192+k)*64+j];
}

__global__ void prep_w2(const float* __restrict__ W2) {
    int e = blockIdx.x*256 + threadIdx.x;           // over 128*RST = 9216
    if (e >= 128*RST) return;
    int k = e % RST;
    int n = e / RST;
    if (k >= 64) { g_B2hi[e] = __float2bfloat16(0.f); g_B2lo[e] = __float2bfloat16(0.f); return; }
    int h = n >> 5, j = n & 31;
    float v = W2[h*2048 + k*32 + j];
    __nv_bfloat16 hi = __float2bfloat16(v);
    g_B2hi[e] = hi;
    g_B2lo[e] = __float2bfloat16(v - __bfloat162float(hi));
}

__global__ void prep_c1(const float* __restrict__ query, const float* __restrict__ b1) {
    __shared__ float sq[32*64];
    int tid = threadIdx.x;
    int b0 = blockIdx.x * 32;
    for (int t = tid; t < 32*64; t += 256) sq[t] = query[b0*64 + t];
    __syncthreads();
    int h = tid >> 6, j = tid & 63;
    float bias = b1[h*64 + j];
    float acc[32];
    #pragma unroll
    for (int bb = 0; bb < 32; bb++) acc[bb] = bias;
    const float* wcol = g_W1c + h*4096 + j;
    #pragma unroll 4
    for (int i = 0; i < 64; i++) {
        float wv = wcol[i*64];
        #pragma unroll
        for (int bb = 0; bb < 32; bb++) acc[bb] = fmaf(sq[bb*64 + i], wv, acc[bb]);
    }
    for (int bb = 0; bb < 32; bb++) g_C1[(b0+bb)*256 + tid] = acc[bb];
}

// ---- helpers ----
__device__ __forceinline__ uint32_t pkbf(__nv_bfloat16 a, __nv_bfloat16 b) {
    __nv_bfloat162 t = __halves2bfloat162(a, b);
    return *reinterpret_cast<uint32_t*>(&t);
}
__device__ __forceinline__ void split2(float x, float y, uint32_t& hi, uint32_t& lo) {
    __nv_bfloat16 hx = __float2bfloat16(x), hy = __float2bfloat16(y);
    hi = pkbf(hx, hy);
    lo = pkbf(__float2bfloat16(x - __bfloat162float(hx)),
              __float2bfloat16(y - __bfloat162float(hy)));
}
__device__ __forceinline__ void mma16816(float* d, const uint32_t* a, const uint32_t* b) {
    asm volatile("mma.sync.aligned.m16n8k16.row.col.f32.bf16.bf16.f32 "
        "{%0,%1,%2,%3}, {%4,%5,%6,%7}, {%8,%9}, {%0,%1,%2,%3};"
        : "+f"(d[0]), "+f"(d[1]), "+f"(d[2]), "+f"(d[3])
        : "r"(a[0]), "r"(a[1]), "r"(a[2]), "r"(a[3]), "r"(b[0]), "r"(b[1]));
}
__device__ __forceinline__ void ldm4(uint32_t& r0, uint32_t& r1, uint32_t& r2, uint32_t& r3,
                                     uint32_t addr) {
    asm volatile("ldmatrix.sync.aligned.m8n8.x4.shared.b16 {%0,%1,%2,%3}, [%4];"
        : "=r"(r0), "=r"(r1), "=r"(r2), "=r"(r3) : "r"(addr));
}

// ---- smem layout (bytes) ----
#define SM_AHI   0          // keys hi [s=256][RST] bf16 = 36864
#define SM_ALO   36864
#define SM_B1HI  73728      // W1ab^T hi [n=256][RST]
#define SM_B1LO  110592
#define SM_B2HI  147456     // W2^T hi [n=128][RST] = 18432
#define SM_B2LO  165888
#define SM_SC    184320     // 4*208 f32
#define SM_C1    187648     // 256 f32
#define SM_MASK  188672     // 208 f32 (+pad)
#define SM_W3    189504     // 128 f32
#define SM_B2B   190016     // 128 f32
#define SM_MISC  190528     // b3[0..3] a1[4..7] a2[8..11] comb[16..79]
#define SM_Q     190912     // 64 f32
#define SM_OUTH  191168     // 256 f32
#define SMEM_BYTES 192192
// Phase E reuses [0 .. 54272) (dead A-tile region) for fp32 keys [64][KST]

__global__ __launch_bounds__(NTHR, 1)
void attn_main(const float* __restrict__ query,
               const float* __restrict__ keys,
               const int*   __restrict__ kmask,
               const float* __restrict__ a1,
               const float* __restrict__ b2,
               const float* __restrict__ a2,
               const float* __restrict__ W3,
               const float* __restrict__ b3,
               const float* __restrict__ Wo,
               const float* __restrict__ bo,
               float* __restrict__ out)
{
    extern __shared__ char smc[];
    float* sScf  = (float*)(smc + SM_SC);
    float* sC1f  = (float*)(smc + SM_C1);
    float* sMaskf= (float*)(smc + SM_MASK);
    float* sW3f  = (float*)(smc + SM_W3);
    float* sB2bf = (float*)(smc + SM_B2B);
    float* sMiscf= (float*)(smc + SM_MISC);
    float* sQf   = (float*)(smc + SM_Q);
    float* sOutH = (float*)(smc + SM_OUTH);
    float* sKf   = (float*)(smc);          // Phase E only
    const uint32_t smb = (uint32_t)__cvta_generic_to_shared(smc);

    const int b = blockIdx.x;
    const int tid = threadIdx.x;
    const int wid = tid >> 5, lane = tid & 31;
    const int gc = lane & 3;

    // ---- Phase A ----
    for (int t = tid; t < 256; t += NTHR) sC1f[t] = g_C1[b*256 + t];
    if (tid < NH*NH2) { sW3f[tid] = W3[tid]; sB2bf[tid] = b2[tid]; }
    if (tid < ND) sQf[tid] = query[b*ND + tid];
    if (tid < NH) { sMiscf[tid] = b3[tid]; sMiscf[4+tid] = a1[tid]; sMiscf[8+tid] = a2[tid]; }
    if (tid < NSP) {
        float v = 0.f;
        if (tid < NS) v = (kmask[b*NS + tid] != 0) ? 1.f : 0.f;
        sMaskf[tid] = v;
    }
    for (int t = tid; t < 1152; t += NTHR) {
        ((uint4*)(smc+SM_B2HI))[t] = ((const uint4*)g_B2hi)[t];
        ((uint4*)(smc+SM_B2LO))[t] = ((const uint4*)g_B2lo)[t];
    }
    for (int t = tid; t < 504; t += NTHR) {
        ((uint4*)(smc + SM_AHI + 200*144))[t] = make_uint4(0,0,0,0);
        ((uint4*)(smc + SM_ALO + 200*144))[t] = make_uint4(0,0,0,0);
    }
    {
        const float4* kg = (const float4*)(keys + (size_t)b * (NS*ND));
        for (int t = tid; t < 3200; t += NTHR) {
            float4 v = kg[t];
            int e = t*4, s = e>>6, k = e&63;
            uint32_t h01, l01, h23, l23;
            split2(v.x, v.y, h01, l01);
            split2(v.z, v.w, h23, l23);
            uint32_t off = (uint32_t)(s*RST + k) * 2u;
            *(uint2*)(smc + SM_AHI + off) = make_uint2(h01, h23);
            *(uint2*)(smc + SM_ALO + off) = make_uint2(l01, l23);
        }
    }
    __syncthreads();   // sQf ready for fold

    // B1 fold: 2 adjacent k per thread, uint32 stores
    for (int t = tid; t < 8192; t += NTHR) {
        int k = (t & 31) * 2, n = t >> 5;
        int e = n*64 + k;
        float va = fmaf(sQf[k],   g_W1bT[e],   g_W1aT[e]);
        float vb = fmaf(sQf[k+1], g_W1bT[e+1], g_W1aT[e+1]);
        uint32_t hi, lo;
        split2(va, vb, hi, lo);
        uint32_t off = (uint32_t)(n*RST + k) * 2u;
        *(uint32_t*)(smc + SM_B1HI + off) = hi;
        *(uint32_t*)(smc + SM_B1LO + off) = lo;
    }
    __syncthreads();

    // ---- ldmatrix lane offsets ----
    const int lm = lane >> 3;            // matrix index 0..3
    const int lr = lane & 7;             // row within matrix
    // A tiles: matrices = (rows0-7,k0-7),(rows8-15,k0-7),(rows0-7,k8-15),(rows8-15,k8-15)
    const uint32_t aOff = (uint32_t)(((wid*16 + (lm&1)*8 + lr)*RST + (lm>>1)*8) * 2);
    // B tiles: group q covers 2 nf (16 rows); matrices = (nf0,k0-7),(nf0,k8-15),(nf1,k0-7),(nf1,k8-15)
    const uint32_t bOff = (uint32_t)((((lm>>1)*8 + lr)*RST + (lm&1)*8) * 2);

    // ---- load A fragments once (16 rows/warp, reused for all heads) ----
    uint32_t ahi[4][4], alo[4][4];
    #pragma unroll
    for (int kc = 0; kc < 4; kc++) {
        ldm4(ahi[kc][0], ahi[kc][1], ahi[kc][2], ahi[kc][3], smb + SM_AHI + aOff + kc*32);
        ldm4(alo[kc][0], alo[kc][1], alo[kc][2], alo[kc][3], smb + SM_ALO + aOff + kc*32);
    }

    // ---- Phase C: per-head GEMM1 -> epilogue -> GEMM2 -> scores ----
    #pragma unroll 1
    for (int h = 0; h < NH; h++) {
        const float al1 = sMiscf[4+h];
        const float al2 = sMiscf[8+h];

        float acc[8][4];
        #pragma unroll
        for (int nf = 0; nf < 8; nf++)
            #pragma unroll
            for (int r = 0; r < 4; r++) acc[nf][r] = 0.f;

        // 3 passes: (Ahi,B1hi), (Ahi,B1lo), (Alo,B1hi)
        #pragma unroll 1
        for (int pass = 0; pass < 3; pass++) {
            const uint32_t bbase = smb + ((pass == 1) ? SM_B1LO : SM_B1HI)
                                 + (uint32_t)(h*64*RST*2) + bOff;
            const uint32_t (*A)[4] = (pass == 2) ? alo : ahi;
            #pragma unroll
            for (int kc = 0; kc < 4; kc++) {
                uint32_t bf[8][2];
                #pragma unroll
                for (int q = 0; q < 4; q++)
                    ldm4(bf[2*q][0], bf[2*q][1], bf[2*q+1][0], bf[2*q+1][1],
                         bbase + (uint32_t)(q*16*RST*2) + kc*32);
                #pragma unroll
                for (int nf = 0; nf < 8; nf++)
                    mma16816(acc[nf], A[kc], bf[nf]);
            }
        }

        // epilogue 1: +c1, PReLU -> split into A2 fragments (C->A remap)
        uint32_t a2h[4][4], a2l[4][4];
        #pragma unroll
        for (int nf = 0; nf < 8; nf++) {
            float2 c1v = *(const float2*)(sC1f + h*64 + nf*8 + 2*gc);
            float v0 = acc[nf][0] + c1v.x;
            float v1 = acc[nf][1] + c1v.y;
            float v2 = acc[nf][2] + c1v.x;
            float v3 = acc[nf][3] + c1v.y;
            acc[nf][0] = v0 > 0.f ? v0 : al1*v0;
            acc[nf][1] = v1 > 0.f ? v1 : al1*v1;
            acc[nf][2] = v2 > 0.f ? v2 : al1*v2;
            acc[nf][3] = v3 > 0.f ? v3 : al1*v3;
        }
        #pragma unroll
        for (int kc = 0; kc < 4; kc++) {
            const float* cA = acc[2*kc];
            const float* cB = acc[2*kc+1];
            split2(cA[0], cA[1], a2h[kc][0], a2l[kc][0]);
            split2(cA[2], cA[3], a2h[kc][1], a2l[kc][1]);
            split2(cB[0], cB[1], a2h[kc][2], a2l[kc][2]);
            split2(cB[2], cB[3], a2h[kc][3], a2l[kc][3]);
        }

        // GEMM2: acc2[4n]
        float acc2[4][4];
        #pragma unroll
        for (int nf = 0; nf < 4; nf++)
            #pragma unroll
            for (int r = 0; r < 4; r++) acc2[nf][r] = 0.f;

        #pragma unroll 1
        for (int pass = 0; pass < 3; pass++) {
            const uint32_t bbase = smb + ((pass == 1) ? SM_B2LO : SM_B2HI)
                                 + (uint32_t)(h*32*RST*2) + bOff;
            const uint32_t (*A)[4] = (pass == 2) ? a2l : a2h;
            #pragma unroll
            for (int kc = 0; kc < 4; kc++) {
                uint32_t bf[4][2];
                #pragma unroll
                for (int q = 0; q < 2; q++)
                    ldm4(bf[2*q][0], bf[2*q][1], bf[2*q+1][0], bf[2*q+1][1],
                         bbase + (uint32_t)(q*16*RST*2) + kc*32);
                #pragma unroll
                for (int nf = 0; nf < 4; nf++)
                    mma16816(acc2[nf], A[kc], bf[nf]);
            }
        }

        // epilogue 2: +b2, PReLU, dot W3, 4-lane reduce -> scores
        const float b3h = sMiscf[h];
        {
            float p0 = 0.f, p1 = 0.f;
            #pragma unroll
            for (int nf = 0; nf < 4; nf++) {
                int j0 = h*32 + nf*8 + 2*gc;
                float2 bb = *(const float2*)(sB2bf + j0);
                float2 ww = *(const float2*)(sW3f + j0);
                float v0 = acc2[nf][0] + bb.x;
                float v1 = acc2[nf][1] + bb.y;
                float v2 = acc2[nf][2] + bb.x;
                float v3 = acc2[nf][3] + bb.y;
                v0 = v0 > 0.f ? v0 : al2*v0;
                v1 = v1 > 0.f ? v1 : al2*v1;
                v2 = v2 > 0.f ? v2 : al2*v2;
                v3 = v3 > 0.f ? v3 : al2*v3;
                p0 = fmaf(v0, ww.x, fmaf(v1, ww.y, p0));
                p1 = fmaf(v2, ww.x, fmaf(v3, ww.y, p1));
            }
            p0 += __shfl_xor_sync(0xffffffffu, p0, 1);
            p0 += __shfl_xor_sync(0xffffffffu, p0, 2);
            p1 += __shfl_xor_sync(0xffffffffu, p1, 1);
            p1 += __shfl_xor_sync(0xffffffffu, p1, 2);
            if (gc == 0) {
                int gr = lane >> 2;
                int s = wid*16 + gr;
                if (s < NSP)   sScf[h*NSP + s]   = (sMaskf[s]   != 0.f) ? (p0 + b3h) : -FLT_MAX;
                if (s+8 < NSP) sScf[h*NSP + s+8] = (sMaskf[s+8] != 0.f) ? (p1 + b3h) : -FLT_MAX;
            }
        }
    }
    __syncthreads();

    // ---- Phase D (warps 0-3) overlapped with fp32-keys reload (warps 4-15) ----
    if (wid < NH) {
        float* row = sScf + wid*NSP;
        float m = -FLT_MAX;
        for (int t = lane; t < NS; t += 32) m = fmaxf(m, row[t]);
        #pragma unroll
        for (int o = 16; o > 0; o >>= 1) m = fmaxf(m, __shfl_xor_sync(0xffffffffu, m, o));
        float sum = 0.f;
        for (int t = lane; t < NS; t += 32) {
            float v = row[t];
            float e = (v > -1e38f) ? expf(v - m) : 0.f;
            row[t] = e;
            sum += e;
        }
        #pragma unroll
        for (int o = 16; o > 0; o >>= 1) sum += __shfl_xor_sync(0xffffffffu, sum, o);
        float inv = (sum > 0.f) ? (1.f / sum) : 0.f;
        for (int t = lane; t < NS; t += 32) row[t] *= inv;
    } else {
        int t2 = tid - 128;                        // 0..383
        for (int t = t2; t < 768; t += 384) {      // pad cols 200..211
            int d = t / 12, p = 200 + t % 12;
            sKf[d*KST + p] = 0.f;
        }
        const float4* kg = (const float4*)(keys + (size_t)b * (NS*ND));
        for (int t = t2; t < 3200; t += 384) {
            float4 v = kg[t];
            int e = t*4, s = e>>6, d = e&63;
            float* dst = sKf + d*KST + s;
            dst[0*KST]=v.x; dst[1*KST]=v.y; dst[2*KST]=v.z; dst[3*KST]=v.w;
        }
    }
    __syncthreads();

    // ---- Phase E: weighted sum, head mean, out projection ----
    if (tid < NH*ND) {
        int h = tid >> 6, d = tid & 63;
        const float* w    = sScf + h*NSP;
        const float* kcol = sKf + d*KST;
        float a0 = 0.f, a1_ = 0.f, a2_ = 0.f, a3_ = 0.f;
        #pragma unroll 4
        for (int t = 0; t < NS; t += 4) {
            a0  = fmaf(w[t  ], kcol[t  ], a0);
            a1_ = fmaf(w[t+1], kcol[t+1], a1_);
            a2_ = fmaf(w[t+2], kcol[t+2], a2_);
            a3_ = fmaf(w[t+3], kcol[t+3], a3_);
        }
        sOutH[tid] = (a0 + a1_) + (a2_ + a3_);
    }
    __syncthreads();
    if (tid < ND) {
        float c = 0.25f * (sOutH[tid] + sOutH[64+tid] + sOutH[128+tid] + sOutH[192+tid]);
        sMiscf[16 + tid] = c;
    }
    __syncthreads();
    if (tid < ND) {
        float e0 = bo[tid], e1 = 0.f;
        #pragma unroll 4
        for (int d2 = 0; d2 < ND; d2 += 2) {
            e0 = fmaf(sMiscf[16 + d2],     Wo[(d2  )*ND + tid], e0);
            e1 = fmaf(sMiscf[16 + d2 + 1], Wo[(d2+1)*ND + tid], e1);
        }
        out[b*ND + tid] = e0 + e1;
    }
}

extern "C" void kernel_launch(void* const* d_in, const int* in_sizes, int n_in,
                              void* d_out, int out_size) {
    const float* query = (const float*)d_in[0];
    const float* keys  = (const float*)d_in[1];
    const int*   kmask = (const int*)  d_in[2];
    const float* W1    = (const float*)d_in[3];
    const float* b1    = (const float*)d_in[4];
    const float* a1    = (const float*)d_in[5];
    const float* W2    = (const float*)d_in[6];
    const float* b2    = (const float*)d_in[7];
    const float* a2    = (const float*)d_in[8];
    const float* W3    = (const float*)d_in[9];
    const float* b3    = (const float*)d_in[10];
    const float* Wo    = (const float*)d_in[11];
    const float* bo    = (const float*)d_in[12];
    float* out = (float*)d_out;

    cudaFuncSetAttribute(attn_main, cudaFuncAttributeMaxDynamicSharedMemorySize, SMEM_BYTES);

    prep_w1<<<64, 256>>>(W1);
    prep_w2<<<36, 256>>>(W2);
    prep_c1<<<64, 256>>>(query, b1);
    attn_main<<<NB, NTHR, SMEM_BYTES>>>(
        query, keys, kmask, a1, b2, a2, W3, b3, Wo, bo, out);
}

// round 15
// speedup vs baseline: 2.0834x; 1.0655x over previous
#include <cuda_runtime.h>
#include <cuda_bf16.h>
#include <float.h>
#include <stdint.h>

#define NB 2048
#define NS 200
#define NSP 208
#define ND 64
#define NH 4
#define NH1 64
#define NH2 32
#define KST 213       // odd: Phase-E scalar column reads conflict-free
#define NTHR 512
#define RST 72        // padded row stride (elements) for all bf16 MMA tiles

// ---- global prep buffers ----
__device__ float g_W1aT[16384];           // (Wk+Wd)^T  [n=h*64+j][k]
__device__ float g_W1bT[16384];           // Wkq^T      [n][k]
__device__ float g_W1c[16384];            // Wq-Wd      [h][k][j] (for c1 prep)
__device__ __nv_bfloat16 g_B2hi[128*RST]; // W2^T hi    [n=h*32+j][k] padded rows
__device__ __nv_bfloat16 g_B2lo[128*RST];
__device__ float g_C1[NB*256];            // c1 = q@(Wq-Wd)+b1

__global__ void prep_w1(const float* __restrict__ W1) {
    int e = blockIdx.x*256 + threadIdx.x;           // 0..16383
    if (e >= 16384) return;
    int k = e & 63;
    int n = e >> 6;
    int h = n >> 6, j = n & 63;
    const float* w = W1 + h*256*64;
    g_W1aT[e] = w[k*64+j] + w[(192+k)*64+j];
    g_W1bT[e] = w[(128+k)*64+j];
    g_W1c[h*4096 + k*64 + j] = w[(64+k)*64+j] - w[(192+k)*64+j];
}

__global__ void prep_w2(const float* __restrict__ W2) {
    int e = blockIdx.x*256 + threadIdx.x;           // over 128*RST = 9216
    if (e >= 128*RST) return;
    int k = e % RST;
    int n = e / RST;
    if (k >= 64) { g_B2hi[e] = __float2bfloat16(0.f); g_B2lo[e] = __float2bfloat16(0.f); return; }
    int h = n >> 5, j = n & 31;
    float v = W2[h*2048 + k*32 + j];
    __nv_bfloat16 hi = __float2bfloat16(v);
    g_B2hi[e] = hi;
    g_B2lo[e] = __float2bfloat16(v - __bfloat162float(hi));
}

__global__ void prep_c1(const float* __restrict__ query, const float* __restrict__ b1) {
    __shared__ float sq[32*64];
    int tid = threadIdx.x;
    int b0 = blockIdx.x * 32;
    for (int t = tid; t < 32*64; t += 256) sq[t] = query[b0*64 + t];
    __syncthreads();
    int h = tid >> 6, j = tid & 63;
    float bias = b1[h*64 + j];
    float acc[32];
    #pragma unroll
    for (int bb = 0; bb < 32; bb++) acc[bb] = bias;
    const float* wcol = g_W1c + h*4096 + j;
    #pragma unroll 4
    for (int i = 0; i < 64; i++) {
        float wv = wcol[i*64];
        #pragma unroll
        for (int bb = 0; bb < 32; bb++) acc[bb] = fmaf(sq[bb*64 + i], wv, acc[bb]);
    }
    for (int bb = 0; bb < 32; bb++) g_C1[(b0+bb)*256 + tid] = acc[bb];
}

// ---- helpers ----
__device__ __forceinline__ uint32_t pkbf(__nv_bfloat16 a, __nv_bfloat16 b) {
    __nv_bfloat162 t = __halves2bfloat162(a, b);
    return *reinterpret_cast<uint32_t*>(&t);
}
__device__ __forceinline__ void split2(float x, float y, uint32_t& hi, uint32_t& lo) {
    __nv_bfloat16 hx = __float2bfloat16(x), hy = __float2bfloat16(y);
    hi = pkbf(hx, hy);
    lo = pkbf(__float2bfloat16(x - __bfloat162float(hx)),
              __float2bfloat16(y - __bfloat162float(hy)));
}
__device__ __forceinline__ void mma16816(float* d, const uint32_t* a, const uint32_t* b) {
    asm volatile("mma.sync.aligned.m16n8k16.row.col.f32.bf16.bf16.f32 "
        "{%0,%1,%2,%3}, {%4,%5,%6,%7}, {%8,%9}, {%0,%1,%2,%3};"
        : "+f"(d[0]), "+f"(d[1]), "+f"(d[2]), "+f"(d[3])
        : "r"(a[0]), "r"(a[1]), "r"(a[2]), "r"(a[3]), "r"(b[0]), "r"(b[1]));
}
__device__ __forceinline__ void ldm4(uint32_t& r0, uint32_t& r1, uint32_t& r2, uint32_t& r3,
                                     uint32_t addr) {
    asm volatile("ldmatrix.sync.aligned.m8n8.x4.shared.b16 {%0,%1,%2,%3}, [%4];"
        : "=r"(r0), "=r"(r1), "=r"(r2), "=r"(r3) : "r"(addr));
}

// ---- smem layout (bytes) ----
#define SM_AHI   0          // keys hi [s=256][RST] bf16 = 36864
#define SM_ALO   36864
#define SM_B1HI  73728      // W1ab^T hi [n=256][RST]
#define SM_B1LO  110592
#define SM_B2HI  147456     // W2^T hi [n=128][RST] = 18432
#define SM_B2LO  165888
#define SM_SC    184320     // 4*208 f32
#define SM_C1    187648     // 256 f32
#define SM_MASK  188672     // 208 f32 (+pad)
#define SM_W3    189504     // 128 f32
#define SM_B2B   190016     // 128 f32
#define SM_MISC  190528     // b3[0..3] a1[4..7] a2[8..11] comb[16..79]
#define SM_Q     190912     // 64 f32
#define SM_OUTH  191168     // 256 f32
#define SMEM_BYTES 192192
// Phase E reuses [0 .. 54528) (dead A-tile region) for fp32 keys [64][KST]

__global__ __launch_bounds__(NTHR, 1)
void attn_main(const float* __restrict__ query,
               const float* __restrict__ keys,
               const int*   __restrict__ kmask,
               const float* __restrict__ a1,
               const float* __restrict__ b2,
               const float* __restrict__ a2,
               const float* __restrict__ W3,
               const float* __restrict__ b3,
               const float* __restrict__ Wo,
               const float* __restrict__ bo,
               float* __restrict__ out)
{
    extern __shared__ char smc[];
    float* sScf  = (float*)(smc + SM_SC);
    float* sC1f  = (float*)(smc + SM_C1);
    float* sMaskf= (float*)(smc + SM_MASK);
    float* sW3f  = (float*)(smc + SM_W3);
    float* sB2bf = (float*)(smc + SM_B2B);
    float* sMiscf= (float*)(smc + SM_MISC);
    float* sQf   = (float*)(smc + SM_Q);
    float* sOutH = (float*)(smc + SM_OUTH);
    float* sKf   = (float*)(smc);          // Phase E only
    const uint32_t smb = (uint32_t)__cvta_generic_to_shared(smc);

    const int b = blockIdx.x;
    const int tid = threadIdx.x;
    const int wid = tid >> 5, lane = tid & 31;
    const int gc = lane & 3;

    // ---- Phase A ----
    for (int t = tid; t < 256; t += NTHR) sC1f[t] = g_C1[b*256 + t];
    if (tid < NH*NH2) { sW3f[tid] = W3[tid]; sB2bf[tid] = b2[tid]; }
    if (tid < ND) sQf[tid] = query[b*ND + tid];
    if (tid < NH) { sMiscf[tid] = b3[tid]; sMiscf[4+tid] = a1[tid]; sMiscf[8+tid] = a2[tid]; }
    if (tid < NSP) {
        float v = 0.f;
        if (tid < NS) v = (kmask[b*NS + tid] != 0) ? 1.f : 0.f;
        sMaskf[tid] = v;
    }
    for (int t = tid; t < 1152; t += NTHR) {
        ((uint4*)(smc+SM_B2HI))[t] = ((const uint4*)g_B2hi)[t];
        ((uint4*)(smc+SM_B2LO))[t] = ((const uint4*)g_B2lo)[t];
    }
    for (int t = tid; t < 504; t += NTHR) {
        ((uint4*)(smc + SM_AHI + 200*144))[t] = make_uint4(0,0,0,0);
        ((uint4*)(smc + SM_ALO + 200*144))[t] = make_uint4(0,0,0,0);
    }
    {
        const float4* kg = (const float4*)(keys + (size_t)b * (NS*ND));
        for (int t = tid; t < 3200; t += NTHR) {
            float4 v = kg[t];
            int e = t*4, s = e>>6, k = e&63;
            uint32_t h01, l01, h23, l23;
            split2(v.x, v.y, h01, l01);
            split2(v.z, v.w, h23, l23);
            uint32_t off = (uint32_t)(s*RST + k) * 2u;
            *(uint2*)(smc + SM_AHI + off) = make_uint2(h01, h23);
            *(uint2*)(smc + SM_ALO + off) = make_uint2(l01, l23);
        }
    }
    __syncthreads();   // sQf ready for fold

    // B1 fold: 2 adjacent k per thread, uint32 stores
    for (int t = tid; t < 8192; t += NTHR) {
        int k = (t & 31) * 2, n = t >> 5;
        int e = n*64 + k;
        float va = fmaf(sQf[k],   g_W1bT[e],   g_W1aT[e]);
        float vb = fmaf(sQf[k+1], g_W1bT[e+1], g_W1aT[e+1]);
        uint32_t hi, lo;
        split2(va, vb, hi, lo);
        uint32_t off = (uint32_t)(n*RST + k) * 2u;
        *(uint32_t*)(smc + SM_B1HI + off) = hi;
        *(uint32_t*)(smc + SM_B1LO + off) = lo;
    }
    __syncthreads();

    // ---- ldmatrix lane offsets ----
    const int lm = lane >> 3;            // matrix index 0..3
    const int lr = lane & 7;             // row within matrix
    const uint32_t aOff = (uint32_t)(((wid*16 + (lm&1)*8 + lr)*RST + (lm>>1)*8) * 2);
    const uint32_t bOff = (uint32_t)((((lm>>1)*8 + lr)*RST + (lm&1)*8) * 2);

    // ---- load A fragments once (16 rows/warp, reused for all heads) ----
    uint32_t ahi[4][4], alo[4][4];
    #pragma unroll
    for (int kc = 0; kc < 4; kc++) {
        ldm4(ahi[kc][0], ahi[kc][1], ahi[kc][2], ahi[kc][3], smb + SM_AHI + aOff + kc*32);
        ldm4(alo[kc][0], alo[kc][1], alo[kc][2], alo[kc][3], smb + SM_ALO + aOff + kc*32);
    }

    // ---- Phase C: per-head GEMM1 -> epilogue -> GEMM2 -> scores ----
    #pragma unroll 1
    for (int h = 0; h < NH; h++) {
        const float al1 = sMiscf[4+h];
        const float al2 = sMiscf[8+h];

        float acc[8][4];
        #pragma unroll
        for (int nf = 0; nf < 8; nf++)
            #pragma unroll
            for (int r = 0; r < 4; r++) acc[nf][r] = 0.f;

        // B1hi loop: feeds BOTH (ahi x bhi) and (alo x bhi)
        {
            const uint32_t bbase = smb + SM_B1HI + (uint32_t)(h*64*RST*2) + bOff;
            #pragma unroll
            for (int kc = 0; kc < 4; kc++) {
                uint32_t bf[8][2];
                #pragma unroll
                for (int q = 0; q < 4; q++)
                    ldm4(bf[2*q][0], bf[2*q][1], bf[2*q+1][0], bf[2*q+1][1],
                         bbase + (uint32_t)(q*16*RST*2) + kc*32);
                #pragma unroll
                for (int nf = 0; nf < 8; nf++)
                    mma16816(acc[nf], ahi[kc], bf[nf]);
                #pragma unroll
                for (int nf = 0; nf < 8; nf++)
                    mma16816(acc[nf], alo[kc], bf[nf]);
            }
        }
        // B1lo loop: feeds (ahi x blo) only
        {
            const uint32_t bbase = smb + SM_B1LO + (uint32_t)(h*64*RST*2) + bOff;
            #pragma unroll
            for (int kc = 0; kc < 4; kc++) {
                uint32_t bf[8][2];
                #pragma unroll
                for (int q = 0; q < 4; q++)
                    ldm4(bf[2*q][0], bf[2*q][1], bf[2*q+1][0], bf[2*q+1][1],
                         bbase + (uint32_t)(q*16*RST*2) + kc*32);
                #pragma unroll
                for (int nf = 0; nf < 8; nf++)
                    mma16816(acc[nf], ahi[kc], bf[nf]);
            }
        }

        // epilogue 1: +c1, PReLU -> split into A2 fragments (C->A remap)
        uint32_t a2h[4][4], a2l[4][4];
        #pragma unroll
        for (int nf = 0; nf < 8; nf++) {
            float2 c1v = *(const float2*)(sC1f + h*64 + nf*8 + 2*gc);
            float v0 = acc[nf][0] + c1v.x;
            float v1 = acc[nf][1] + c1v.y;
            float v2 = acc[nf][2] + c1v.x;
            float v3 = acc[nf][3] + c1v.y;
            acc[nf][0] = v0 > 0.f ? v0 : al1*v0;
            acc[nf][1] = v1 > 0.f ? v1 : al1*v1;
            acc[nf][2] = v2 > 0.f ? v2 : al1*v2;
            acc[nf][3] = v3 > 0.f ? v3 : al1*v3;
        }
        #pragma unroll
        for (int kc = 0; kc < 4; kc++) {
            const float* cA = acc[2*kc];
            const float* cB = acc[2*kc+1];
            split2(cA[0], cA[1], a2h[kc][0], a2l[kc][0]);
            split2(cA[2], cA[3], a2h[kc][1], a2l[kc][1]);
            split2(cB[0], cB[1], a2h[kc][2], a2l[kc][2]);
            split2(cB[2], cB[3], a2h[kc][3], a2l[kc][3]);
        }

        // GEMM2: acc2[4n]
        float acc2[4][4];
        #pragma unroll
        for (int nf = 0; nf < 4; nf++)
            #pragma unroll
            for (int r = 0; r < 4; r++) acc2[nf][r] = 0.f;

        // B2hi loop: feeds (a2h x bhi) and (a2l x bhi)
        {
            const uint32_t bbase = smb + SM_B2HI + (uint32_t)(h*32*RST*2) + bOff;
            #pragma unroll
            for (int kc = 0; kc < 4; kc++) {
                uint32_t bf[4][2];
                #pragma unroll
                for (int q = 0; q < 2; q++)
                    ldm4(bf[2*q][0], bf[2*q][1], bf[2*q+1][0], bf[2*q+1][1],
                         bbase + (uint32_t)(q*16*RST*2) + kc*32);
                #pragma unroll
                for (int nf = 0; nf < 4; nf++)
                    mma16816(acc2[nf], a2h[kc], bf[nf]);
                #pragma unroll
                for (int nf = 0; nf < 4; nf++)
                    mma16816(acc2[nf], a2l[kc], bf[nf]);
            }
        }
        // B2lo loop: feeds (a2h x blo)
        {
            const uint32_t bbase = smb + SM_B2LO + (uint32_t)(h*32*RST*2) + bOff;
            #pragma unroll
            for (int kc = 0; kc < 4; kc++) {
                uint32_t bf[4][2];
                #pragma unroll
                for (int q = 0; q < 2; q++)
                    ldm4(bf[2*q][0], bf[2*q][1], bf[2*q+1][0], bf[2*q+1][1],
                         bbase + (uint32_t)(q*16*RST*2) + kc*32);
                #pragma unroll
                for (int nf = 0; nf < 4; nf++)
                    mma16816(acc2[nf], a2h[kc], bf[nf]);
            }
        }

        // epilogue 2: +b2, PReLU, dot W3, 4-lane reduce -> scores
        const float b3h = sMiscf[h];
        {
            float p0 = 0.f, p1 = 0.f;
            #pragma unroll
            for (int nf = 0; nf < 4; nf++) {
                int j0 = h*32 + nf*8 + 2*gc;
                float2 bb = *(const float2*)(sB2bf + j0);
                float2 ww = *(const float2*)(sW3f + j0);
                float v0 = acc2[nf][0] + bb.x;
                float v1 = acc2[nf][1] + bb.y;
                float v2 = acc2[nf][2] + bb.x;
                float v3 = acc2[nf][3] + bb.y;
                v0 = v0 > 0.f ? v0 : al2*v0;
                v1 = v1 > 0.f ? v1 : al2*v1;
                v2 = v2 > 0.f ? v2 : al2*v2;
                v3 = v3 > 0.f ? v3 : al2*v3;
                p0 = fmaf(v0, ww.x, fmaf(v1, ww.y, p0));
                p1 = fmaf(v2, ww.x, fmaf(v3, ww.y, p1));
            }
            p0 += __shfl_xor_sync(0xffffffffu, p0, 1);
            p0 += __shfl_xor_sync(0xffffffffu, p0, 2);
            p1 += __shfl_xor_sync(0xffffffffu, p1, 1);
            p1 += __shfl_xor_sync(0xffffffffu, p1, 2);
            if (gc == 0) {
                int gr = lane >> 2;
                int s = wid*16 + gr;
                if (s < NSP)   sScf[h*NSP + s]   = (sMaskf[s]   != 0.f) ? (p0 + b3h) : -FLT_MAX;
                if (s+8 < NSP) sScf[h*NSP + s+8] = (sMaskf[s+8] != 0.f) ? (p1 + b3h) : -FLT_MAX;
            }
        }
    }
    __syncthreads();

    // ---- Phase D (warps 0-3) overlapped with fp32-keys reload (warps 4-15) ----
    if (wid < NH) {
        float* row = sScf + wid*NSP;
        float m = -FLT_MAX;
        for (int t = lane; t < NS; t += 32) m = fmaxf(m, row[t]);
        #pragma unroll
        for (int o = 16; o > 0; o >>= 1) m = fmaxf(m, __shfl_xor_sync(0xffffffffu, m, o));
        float sum = 0.f;
        for (int t = lane; t < NS; t += 32) {
            float v = row[t];
            float e = (v > -1e38f) ? expf(v - m) : 0.f;
            row[t] = e;
            sum += e;
        }
        #pragma unroll
        for (int o = 16; o > 0; o >>= 1) sum += __shfl_xor_sync(0xffffffffu, sum, o);
        float inv = (sum > 0.f) ? (1.f / sum) : 0.f;
        for (int t = lane; t < NS; t += 32) row[t] *= inv;
    } else {
        int t2 = tid - 128;                        // 0..383
        for (int t = t2; t < 832; t += 384) {      // pad cols 200..212
            int d = t / 13, p = 200 + t % 13;
            sKf[d*KST + p] = 0.f;
        }
        const float4* kg = (const float4*)(keys + (size_t)b * (NS*ND));
        for (int t = t2; t < 3200; t += 384) {
            float4 v = kg[t];
            int e = t*4, s = e>>6, d = e&63;
            float* dst = sKf + d*KST + s;
            dst[0*KST]=v.x; dst[1*KST]=v.y; dst[2*KST]=v.z; dst[3*KST]=v.w;
        }
    }
    __syncthreads();

    // ---- Phase E: weighted sum, head mean, out projection ----
    if (tid < NH*ND) {
        int h = tid >> 6, d = tid & 63;
        const float* w    = sScf + h*NSP;
        const float* kcol = sKf + d*KST;
        float a0 = 0.f, a1_ = 0.f, a2_ = 0.f, a3_ = 0.f;
        #pragma unroll 4
        for (int t = 0; t < NS; t += 4) {
            a0  = fmaf(w[t  ], kcol[t  ], a0);
            a1_ = fmaf(w[t+1], kcol[t+1], a1_);
            a2_ = fmaf(w[t+2], kcol[t+2], a2_);
            a3_ = fmaf(w[t+3], kcol[t+3], a3_);
        }
        sOutH[tid] = (a0 + a1_) + (a2_ + a3_);
    }
    __syncthreads();
    if (tid < ND) {
        float c = 0.25f * (sOutH[tid] + sOutH[64+tid] + sOutH[128+tid] + sOutH[192+tid]);
        sMiscf[16 + tid] = c;
    }
    __syncthreads();
    if (tid < ND) {
        float e0 = bo[tid], e1 = 0.f;
        #pragma unroll 4
        for (int d2 = 0; d2 < ND; d2 += 2) {
            e0 = fmaf(sMiscf[16 + d2],     Wo[(d2  )*ND + tid], e0);
            e1 = fmaf(sMiscf[16 + d2 + 1], Wo[(d2+1)*ND + tid], e1);
        }
        out[b*ND + tid] = e0 + e1;
    }
}

extern "C" void kernel_launch(void* const* d_in, const int* in_sizes, int n_in,
                              void* d_out, int out_size) {
    const float* query = (const float*)d_in[0];
    const float* keys  = (const float*)d_in[1];
    const int*   kmask = (const int*)  d_in[2];
    const float* W1    = (const float*)d_in[3];
    const float* b1    = (const float*)d_in[4];
    const float* a1    = (const float*)d_in[5];
    const float* W2    = (const float*)d_in[6];
    const float* b2    = (const float*)d_in[7];
    const float* a2    = (const float*)d_in[8];
    const float* W3    = (const float*)d_in[9];
    const float* b3    = (const float*)d_in[10];
    const float* Wo    = (const float*)d_in[11];
    const float* bo    = (const float*)d_in[12];
    float* out = (float*)d_out;

    cudaFuncSetAttribute(attn_main, cudaFuncAttributeMaxDynamicSharedMemorySize, SMEM_BYTES);

    prep_w1<<<64, 256>>>(W1);
    prep_w2<<<36, 256>>>(W2);
    prep_c1<<<64, 256>>>(query, b1);
    attn_main<<<NB, NTHR, SMEM_BYTES>>>(
        query, keys, kmask, a1, b2, a2, W3, b3, Wo, bo, out);
}